// round 6
// baseline (speedup 1.0000x reference)
#include <cuda_runtime.h>
#include <cuda_bf16.h>
#include <math.h>
#include <stdint.h>

// ---------------------------------------------------------------------------
// Problem constants
// ---------------------------------------------------------------------------
#define NG     8
#define NC     256
#define NL     4096
#define NST    8
#define NRK    16
#define NEDBL  32
#define NCHUNK 32
#define CHUNK  128
#define NDEPTH 4

// ---------------------------------------------------------------------------
// Scratch
// ---------------------------------------------------------------------------
__device__ float g_x   [NG * NL * NC];            // residual stream (g,l,c)
__device__ float g_xz  [NG * NL * 2 * NC];        // in_proj out [xx|z]
__device__ float g_xdbl[2 * NG * NL * NEDBL];     // x_proj out (dt|B|C)
__device__ float g_y0  [NG * NL * NC];            // fwd raw scan out
__device__ float g_y1  [NG * NL * NC];            // bwd raw scan out
__device__ float g_gl  [NG * NL * NC];            // out_proj out
__device__ float g_ap  [2 * NG * NCHUNK * NST * NC];
__device__ float g_hend[2 * NG * NCHUNK * NST * NC];
__device__ float g_hin [2 * NG * NCHUNK * NST * NC];
__device__ __nv_bfloat16 g_xnh[NG * NL * NC], g_xnl[NG * NL * NC];    // ln1 split
__device__ __nv_bfloat16 g_xch[2 * NG * NL * NC], g_xcl[2 * NG * NL * NC]; // conv split
__device__ __nv_bfloat16 g_wih[NDEPTH * 512 * NC], g_wil[NDEPTH * 512 * NC];
__device__ __nv_bfloat16 g_wxh[NDEPTH * NEDBL * NC], g_wxl[NDEPTH * NEDBL * NC];
__device__ __nv_bfloat16 g_woh[NDEPTH * NC * NC], g_wol[NDEPTH * NC * NC];

// ---------------------------------------------------------------------------
// Helpers
// ---------------------------------------------------------------------------
__device__ __forceinline__ uint32_t smem_u32(const void* p) {
    uint32_t a;
    asm("{ .reg .u64 t; cvta.to.shared.u64 t, %1; cvt.u32.u64 %0, t; }" : "=r"(a) : "l"(p));
    return a;
}
__device__ __forceinline__ uint32_t pack2(__nv_bfloat16 a, __nv_bfloat16 b) {
    __nv_bfloat162 t(a, b);
    return *reinterpret_cast<uint32_t*>(&t);
}
__device__ __forceinline__ void bsplit(float v, __nv_bfloat16& h, __nv_bfloat16& l) {
    h = __float2bfloat16(v);
    l = __float2bfloat16(v - __bfloat162float(h));
}
__device__ __forceinline__ void cp16(uint32_t dst, const void* src) {
    asm volatile("cp.async.cg.shared.global [%0], [%1], 16;" :: "r"(dst), "l"(src));
}
__device__ __forceinline__ void cp_commit() {
    asm volatile("cp.async.commit_group;" ::: "memory");
}
__device__ __forceinline__ void cp_wait1() {
    asm volatile("cp.async.wait_group 1;" ::: "memory");
}
__device__ __forceinline__ void ldsm_x4(uint32_t& r0, uint32_t& r1, uint32_t& r2,
                                        uint32_t& r3, uint32_t addr) {
    asm volatile("ldmatrix.sync.aligned.m8n8.x4.shared.b16 {%0,%1,%2,%3}, [%4];"
                 : "=r"(r0), "=r"(r1), "=r"(r2), "=r"(r3) : "r"(addr));
}
__device__ __forceinline__ void ldsm_x2(uint32_t& r0, uint32_t& r1, uint32_t addr) {
    asm volatile("ldmatrix.sync.aligned.m8n8.x2.shared.b16 {%0,%1}, [%2];"
                 : "=r"(r0), "=r"(r1) : "r"(addr));
}
__device__ __forceinline__ void mma_bf16(float* d, const uint32_t* a, const uint32_t* b) {
    asm volatile("mma.sync.aligned.m16n8k16.row.col.f32.bf16.bf16.f32 "
                 "{%0,%1,%2,%3}, {%4,%5,%6,%7}, {%8,%9}, {%0,%1,%2,%3};"
                 : "+f"(d[0]), "+f"(d[1]), "+f"(d[2]), "+f"(d[3])
                 : "r"(a[0]), "r"(a[1]), "r"(a[2]), "r"(a[3]), "r"(b[0]), "r"(b[1]));
}

// ---------------------------------------------------------------------------
// Weight split (fp32 -> bf16 hi/lo), once per launch
// ---------------------------------------------------------------------------
__global__ void __launch_bounds__(256) wsplit_kernel(const float* __restrict__ w,
                                                     __nv_bfloat16* __restrict__ h,
                                                     __nv_bfloat16* __restrict__ l, int n) {
    int i = blockIdx.x * 256 + threadIdx.x;
    if (i < n) {
        __nv_bfloat16 hh, ll;
        bsplit(w[i], hh, ll);
        h[i] = hh; l[i] = ll;
    }
}

// ---------------------------------------------------------------------------
// Segment mean + transpose
// ---------------------------------------------------------------------------
__global__ void __launch_bounds__(256) mean_kernel(const float* __restrict__ data,
                                                   const int* __restrict__ rl) {
    __shared__ float tile[32][33];
    int g  = blockIdx.z;
    int c0 = blockIdx.y * 32;
    int l0 = blockIdx.x * 32;
    int start = 0;
    for (int gg = 0; gg < g; gg++) start += rl[gg];
    int cnt = rl[g];
    float inv = 1.0f / (float)cnt;
    int tx = threadIdx.x;
    for (int r = threadIdx.y; r < 32; r += 8) {
        float s = 0.0f;
        for (int a = 0; a < cnt; a++)
            s += data[((size_t)(start + a) * NC + (c0 + r)) * NL + l0 + tx];
        tile[r][tx] = s * inv;
    }
    __syncthreads();
    for (int r = threadIdx.y; r < 32; r += 8)
        g_x[((size_t)g * NL + (l0 + r)) * NC + c0 + tx] = tile[tx][r];
}

// ---------------------------------------------------------------------------
// LayerNorm
// ---------------------------------------------------------------------------
__device__ __forceinline__ void warp_stats8(const float* o, float& mu, float& rstd) {
    float s = 0.f, s2 = 0.f;
    #pragma unroll
    for (int i = 0; i < 8; i++) { s += o[i]; s2 += o[i] * o[i]; }
    #pragma unroll
    for (int off = 16; off; off >>= 1) {
        s  += __shfl_xor_sync(0xffffffffu, s, off);
        s2 += __shfl_xor_sync(0xffffffffu, s2, off);
    }
    mu = s * (1.0f / NC);
    float var = s2 * (1.0f / NC) - mu * mu;
    rstd = rsqrtf(var + 1e-5f);
}

// LN1 standalone (layer 0): g_x -> xnh/xnl
__global__ void __launch_bounds__(256) ln1_kernel(const float* __restrict__ w,
                                                  const float* __restrict__ b) {
    int row  = blockIdx.x * 8 + (threadIdx.x >> 5);
    int lane = threadIdx.x & 31;
    const float* xr = g_x + (size_t)row * NC + lane * 8;
    float v[8];
    *reinterpret_cast<float4*>(&v[0]) = *(const float4*)(xr);
    *reinterpret_cast<float4*>(&v[4]) = *(const float4*)(xr + 4);
    float mu, rstd;
    warp_stats8(v, mu, rstd);
    __nv_bfloat16 hh[8], ll[8];
    #pragma unroll
    for (int i = 0; i < 8; i++) {
        float o = (v[i] - mu) * rstd * w[lane * 8 + i] + b[lane * 8 + i];
        bsplit(o, hh[i], ll[i]);
    }
    uint4 vh = {pack2(hh[0],hh[1]), pack2(hh[2],hh[3]), pack2(hh[4],hh[5]), pack2(hh[6],hh[7])};
    uint4 vl = {pack2(ll[0],ll[1]), pack2(ll[2],ll[3]), pack2(ll[4],ll[5]), pack2(ll[6],ll[7])};
    *reinterpret_cast<uint4*>(g_xnh + (size_t)row * NC + lane * 8) = vh;
    *reinterpret_cast<uint4*>(g_xnl + (size_t)row * NC + lane * 8) = vl;
}

// Fused: LN2(g_gl)+residual -> g_x, then LN1(next layer) -> xnh/xnl
__global__ void __launch_bounds__(256) ln2ln1_kernel(const float* __restrict__ mw,
                                                     const float* __restrict__ mb,
                                                     const float* __restrict__ lw,
                                                     const float* __restrict__ lb) {
    int row  = blockIdx.x * 8 + (threadIdx.x >> 5);
    int lane = threadIdx.x & 31;
    const float* xr = g_gl + (size_t)row * NC + lane * 8;
    float v[8];
    *reinterpret_cast<float4*>(&v[0]) = *(const float4*)(xr);
    *reinterpret_cast<float4*>(&v[4]) = *(const float4*)(xr + 4);
    float mu, rstd;
    warp_stats8(v, mu, rstd);
    float* srow = g_x + (size_t)row * NC + lane * 8;
    float sk[8];
    *reinterpret_cast<float4*>(&sk[0]) = *(const float4*)(srow);
    *reinterpret_cast<float4*>(&sk[4]) = *(const float4*)(srow + 4);
    float nx[8];
    #pragma unroll
    for (int i = 0; i < 8; i++)
        nx[i] = (v[i] - mu) * rstd * mw[lane * 8 + i] + mb[lane * 8 + i] + sk[i];
    *(float4*)(srow)     = *reinterpret_cast<float4*>(&nx[0]);
    *(float4*)(srow + 4) = *reinterpret_cast<float4*>(&nx[4]);
    float mu2, rstd2;
    warp_stats8(nx, mu2, rstd2);
    __nv_bfloat16 hh[8], ll[8];
    #pragma unroll
    for (int i = 0; i < 8; i++) {
        float o = (nx[i] - mu2) * rstd2 * lw[lane * 8 + i] + lb[lane * 8 + i];
        bsplit(o, hh[i], ll[i]);
    }
    uint4 vh = {pack2(hh[0],hh[1]), pack2(hh[2],hh[3]), pack2(hh[4],hh[5]), pack2(hh[6],hh[7])};
    uint4 vl = {pack2(ll[0],ll[1]), pack2(ll[2],ll[3]), pack2(ll[4],ll[5]), pack2(ll[6],ll[7])};
    *reinterpret_cast<uint4*>(g_xnh + (size_t)row * NC + lane * 8) = vh;
    *reinterpret_cast<uint4*>(g_xnl + (size_t)row * NC + lane * 8) = vl;
}

// LN2 plain (last layer)
__global__ void __launch_bounds__(256) ln2_kernel(const float* __restrict__ w,
                                                  const float* __restrict__ b) {
    int row  = blockIdx.x * 8 + (threadIdx.x >> 5);
    int lane = threadIdx.x & 31;
    const float* xr = g_gl + (size_t)row * NC + lane * 8;
    float v[8];
    *reinterpret_cast<float4*>(&v[0]) = *(const float4*)(xr);
    *reinterpret_cast<float4*>(&v[4]) = *(const float4*)(xr + 4);
    float mu, rstd;
    warp_stats8(v, mu, rstd);
    float* srow = g_x + (size_t)row * NC + lane * 8;
    float sk[8];
    *reinterpret_cast<float4*>(&sk[0]) = *(const float4*)(srow);
    *reinterpret_cast<float4*>(&sk[4]) = *(const float4*)(srow + 4);
    float nx[8];
    #pragma unroll
    for (int i = 0; i < 8; i++)
        nx[i] = (v[i] - mu) * rstd * w[lane * 8 + i] + b[lane * 8 + i] + sk[i];
    *(float4*)(srow)     = *reinterpret_cast<float4*>(&nx[0]);
    *(float4*)(srow + 4) = *reinterpret_cast<float4*>(&nx[4]);
}

// ---------------------------------------------------------------------------
// Pipelined HMMA GEMM (pre-split bf16 A): C = A @ W^T, K=256
//   2-stage cp.async double buffer, dynamic smem.
//   Stage layout (pitch 80B rows): Ah[128][40] | Al[128][40] | Bh[NT][40] | Bl[NT][40]
// ---------------------------------------------------------------------------
template<int NT>
__global__ void __launch_bounds__(256) gemm_pre(const __nv_bfloat16* __restrict__ Ah,
                                                const __nv_bfloat16* __restrict__ Al,
                                                const __nv_bfloat16* __restrict__ Wh,
                                                const __nv_bfloat16* __restrict__ Wl,
                                                float* __restrict__ C, int ldc) {
    constexpr int WN   = (NT == 128) ? 32 : 8;
    constexpr int NSUB = WN / 8;
    constexpr int BOFF = 20480;
    constexpr int STG  = 20480 + 2 * NT * 80;
    extern __shared__ char dsm[];
    const uint32_t sb = smem_u32(dsm);

    const int tid = threadIdx.x, wid = tid >> 5, lane = tid & 31;
    const int l0 = blockIdx.x * 128, n0 = blockIdx.y * NT;
    const size_t aoff = (size_t)blockIdx.z * NL * NC;
    const int wm = (wid & 1) * 64;
    const int wn = (wid >> 1) * WN;
    const int arow = tid >> 1, ahalf = tid & 1;

    float acc[4][NSUB][4];
    #pragma unroll
    for (int mi = 0; mi < 4; mi++)
        #pragma unroll
        for (int ni = 0; ni < NSUB; ni++)
            #pragma unroll
            for (int q = 0; q < 4; q++) acc[mi][ni][q] = 0.0f;

    // stage issue: copy k-chunk kci into buffer buf
    auto issue = [&](int kci, int buf) {
        uint32_t base = sb + buf * STG;
        int kc = kci * 32;
        const __nv_bfloat16* ag = Ah + aoff + (size_t)(l0 + arow) * NC + kc + ahalf * 16;
        const __nv_bfloat16* alg = Al + aoff + (size_t)(l0 + arow) * NC + kc + ahalf * 16;
        uint32_t ad = base + arow * 80 + ahalf * 32;
        cp16(ad, ag);            cp16(ad + 16, ag + 8);
        cp16(ad + 10240, alg);   cp16(ad + 10240 + 16, alg + 8);
        if (NT == 128 || tid < NT * 2) {
            int brow = tid >> 1, bhalf = tid & 1;
            const __nv_bfloat16* bg  = Wh + (size_t)(n0 + brow) * NC + kc + bhalf * 16;
            const __nv_bfloat16* blg = Wl + (size_t)(n0 + brow) * NC + kc + bhalf * 16;
            uint32_t bd = base + BOFF + brow * 80 + bhalf * 32;
            cp16(bd, bg);             cp16(bd + 16, bg + 8);
            cp16(bd + NT * 80, blg);  cp16(bd + NT * 80 + 16, blg + 8);
        }
    };

    issue(0, 0);
    cp_commit();

    for (int kci = 0; kci < 8; kci++) {
        int buf = kci & 1;
        if (kci + 1 < 8) issue(kci + 1, buf ^ 1);
        cp_commit();
        cp_wait1();
        __syncthreads();
        uint32_t abase = sb + buf * STG;
        #pragma unroll
        for (int kk = 0; kk < 32; kk += 16) {
            uint32_t ah[4][4], al[4][4];
            #pragma unroll
            for (int mi = 0; mi < 4; mi++) {
                uint32_t ad = abase + (wm + mi * 16 + (lane & 15)) * 80 + (kk + (lane >> 4) * 8) * 2;
                ldsm_x4(ah[mi][0], ah[mi][1], ah[mi][2], ah[mi][3], ad);
                ldsm_x4(al[mi][0], al[mi][1], al[mi][2], al[mi][3], ad + 10240);
            }
            uint32_t bh[NSUB][2], bl[NSUB][2];
            #pragma unroll
            for (int ni = 0; ni < NSUB; ni++) {
                uint32_t bd = abase + BOFF + (wn + ni * 8 + (lane & 7)) * 80 + (kk + ((lane >> 3) & 1) * 8) * 2;
                ldsm_x2(bh[ni][0], bh[ni][1], bd);
                ldsm_x2(bl[ni][0], bl[ni][1], bd + NT * 80);
            }
            #pragma unroll
            for (int mi = 0; mi < 4; mi++)
                #pragma unroll
                for (int ni = 0; ni < NSUB; ni++) {
                    mma_bf16(acc[mi][ni], ah[mi], bh[ni]);
                    mma_bf16(acc[mi][ni], ah[mi], bl[ni]);
                    mma_bf16(acc[mi][ni], al[mi], bh[ni]);
                }
        }
        __syncthreads();
    }
    float* Cg = C + (size_t)blockIdx.z * NL * ldc;
    #pragma unroll
    for (int mi = 0; mi < 4; mi++)
        #pragma unroll
        for (int ni = 0; ni < NSUB; ni++) {
            int r = l0 + wm + mi * 16 + (lane >> 2);
            int c = n0 + wn + ni * 8 + (lane & 3) * 2;
            float2 v0 = {acc[mi][ni][0], acc[mi][ni][1]};
            float2 v1 = {acc[mi][ni][2], acc[mi][ni][3]};
            *reinterpret_cast<float2*>(Cg + (size_t)r * ldc + c)       = v0;
            *reinterpret_cast<float2*>(Cg + (size_t)(r + 8) * ldc + c) = v1;
        }
}

// ---------------------------------------------------------------------------
// out_proj GEMM with fused gating: A = 0.5*(y0+y1)*silu(z), split in-kernel.
// ---------------------------------------------------------------------------
__global__ void __launch_bounds__(256) gemm_gated(const float* __restrict__ Y0,
                                                  const float* __restrict__ Y1,
                                                  const float* __restrict__ XZ,
                                                  const __nv_bfloat16* __restrict__ Wh,
                                                  const __nv_bfloat16* __restrict__ Wl,
                                                  float* __restrict__ C, int ldc) {
    __shared__ __nv_bfloat16 Ah_s[128][40];
    __shared__ __nv_bfloat16 Al_s[128][40];
    __shared__ __nv_bfloat16 Bh_s[128][40];
    __shared__ __nv_bfloat16 Bl_s[128][40];

    const int tid = threadIdx.x, wid = tid >> 5, lane = tid & 31;
    const int l0 = blockIdx.x * 128, n0 = blockIdx.y * 128, g = blockIdx.z;
    const int wm = (wid & 1) * 64;
    const int wn = (wid >> 1) * 32;
    const int arow = tid >> 1, ahalf = tid & 1;

    float acc[4][4][4];
    #pragma unroll
    for (int mi = 0; mi < 4; mi++)
        #pragma unroll
        for (int ni = 0; ni < 4; ni++)
            #pragma unroll
            for (int q = 0; q < 4; q++) acc[mi][ni][q] = 0.0f;

    for (int kc = 0; kc < NC; kc += 32) {
        // stage A: gated y
        {
            const float* y0 = Y0 + (size_t)g * NL * NC + (size_t)(l0 + arow) * NC + kc + ahalf * 16;
            const float* y1 = Y1 + (size_t)g * NL * NC + (size_t)(l0 + arow) * NC + kc + ahalf * 16;
            const float* zp = XZ + (size_t)g * NL * 512 + (size_t)(l0 + arow) * 512 + 256 + kc + ahalf * 16;
            float f[16];
            #pragma unroll
            for (int q = 0; q < 4; q++) {
                float4 a0 = *reinterpret_cast<const float4*>(y0 + q * 4);
                float4 a1 = *reinterpret_cast<const float4*>(y1 + q * 4);
                float4 zz = *reinterpret_cast<const float4*>(zp + q * 4);
                f[q*4+0] = 0.5f * (a0.x + a1.x) * (zz.x / (1.0f + __expf(-zz.x)));
                f[q*4+1] = 0.5f * (a0.y + a1.y) * (zz.y / (1.0f + __expf(-zz.y)));
                f[q*4+2] = 0.5f * (a0.z + a1.z) * (zz.z / (1.0f + __expf(-zz.z)));
                f[q*4+3] = 0.5f * (a0.w + a1.w) * (zz.w / (1.0f + __expf(-zz.w)));
            }
            __nv_bfloat16 hh[16], ll[16];
            #pragma unroll
            for (int j = 0; j < 16; j++) bsplit(f[j], hh[j], ll[j]);
            uint4 vh0 = {pack2(hh[0],hh[1]),  pack2(hh[2],hh[3]),  pack2(hh[4],hh[5]),  pack2(hh[6],hh[7])};
            uint4 vh1 = {pack2(hh[8],hh[9]),  pack2(hh[10],hh[11]),pack2(hh[12],hh[13]),pack2(hh[14],hh[15])};
            uint4 vl0 = {pack2(ll[0],ll[1]),  pack2(ll[2],ll[3]),  pack2(ll[4],ll[5]),  pack2(ll[6],ll[7])};
            uint4 vl1 = {pack2(ll[8],ll[9]),  pack2(ll[10],ll[11]),pack2(ll[12],ll[13]),pack2(ll[14],ll[15])};
            *reinterpret_cast<uint4*>(&Ah_s[arow][ahalf * 16])     = vh0;
            *reinterpret_cast<uint4*>(&Ah_s[arow][ahalf * 16 + 8]) = vh1;
            *reinterpret_cast<uint4*>(&Al_s[arow][ahalf * 16])     = vl0;
            *reinterpret_cast<uint4*>(&Al_s[arow][ahalf * 16 + 8]) = vl1;
        }
        // stage B
        {
            const __nv_bfloat16* bg  = Wh + (size_t)(n0 + arow) * NC + kc + ahalf * 16;
            const __nv_bfloat16* blg = Wl + (size_t)(n0 + arow) * NC + kc + ahalf * 16;
            uint4 h0 = *reinterpret_cast<const uint4*>(bg);
            uint4 h1 = *reinterpret_cast<const uint4*>(bg + 8);
            uint4 l0v = *reinterpret_cast<const uint4*>(blg);
            uint4 l1v = *reinterpret_cast<const uint4*>(blg + 8);
            *reinterpret_cast<uint4*>(&Bh_s[arow][ahalf * 16])     = h0;
            *reinterpret_cast<uint4*>(&Bh_s[arow][ahalf * 16 + 8]) = h1;
            *reinterpret_cast<uint4*>(&Bl_s[arow][ahalf * 16])     = l0v;
            *reinterpret_cast<uint4*>(&Bl_s[arow][ahalf * 16 + 8]) = l1v;
        }
        __syncthreads();
        #pragma unroll
        for (int kk = 0; kk < 32; kk += 16) {
            uint32_t ah[4][4], al[4][4];
            #pragma unroll
            for (int mi = 0; mi < 4; mi++) {
                uint32_t ad = smem_u32(&Ah_s[wm + mi * 16 + (lane & 15)][kk + (lane >> 4) * 8]);
                ldsm_x4(ah[mi][0], ah[mi][1], ah[mi][2], ah[mi][3], ad);
                ad = smem_u32(&Al_s[wm + mi * 16 + (lane & 15)][kk + (lane >> 4) * 8]);
                ldsm_x4(al[mi][0], al[mi][1], al[mi][2], al[mi][3], ad);
            }
            uint32_t bh[4][2], bl[4][2];
            #pragma unroll
            for (int ni = 0; ni < 4; ni++) {
                uint32_t bd = smem_u32(&Bh_s[wn + ni * 8 + (lane & 7)][kk + ((lane >> 3) & 1) * 8]);
                ldsm_x2(bh[ni][0], bh[ni][1], bd);
                bd = smem_u32(&Bl_s[wn + ni * 8 + (lane & 7)][kk + ((lane >> 3) & 1) * 8]);
                ldsm_x2(bl[ni][0], bl[ni][1], bd);
            }
            #pragma unroll
            for (int mi = 0; mi < 4; mi++)
                #pragma unroll
                for (int ni = 0; ni < 4; ni++) {
                    mma_bf16(acc[mi][ni], ah[mi], bh[ni]);
                    mma_bf16(acc[mi][ni], ah[mi], bl[ni]);
                    mma_bf16(acc[mi][ni], al[mi], bh[ni]);
                }
        }
        __syncthreads();
    }
    float* Cg = C + (size_t)g * NL * ldc;
    #pragma unroll
    for (int mi = 0; mi < 4; mi++)
        #pragma unroll
        for (int ni = 0; ni < 4; ni++) {
            int r = l0 + wm + mi * 16 + (lane >> 2);
            int c = n0 + wn + ni * 8 + (lane & 3) * 2;
            float2 v0 = {acc[mi][ni][0], acc[mi][ni][1]};
            float2 v1 = {acc[mi][ni][2], acc[mi][ni][3]};
            *reinterpret_cast<float2*>(Cg + (size_t)r * ldc + c)       = v0;
            *reinterpret_cast<float2*>(Cg + (size_t)(r + 8) * ldc + c) = v1;
        }
}

// ---------------------------------------------------------------------------
// conv(k=4 causal) + SiLU -> bf16 hi/lo pair
// ---------------------------------------------------------------------------
__global__ void __launch_bounds__(256) conv_silu_kernel(const float* __restrict__ cw,
                                                        const float* __restrict__ cb) {
    int d  = threadIdx.x;
    int l0 = blockIdx.x * 8;
    int dg = blockIdx.y;
    int dir = dg >> 3, g = dg & 7;
    float4 wv = *reinterpret_cast<const float4*>(cw + d * 4);
    float bias = cb[d];
    const float* X = g_xz + (size_t)g * NL * (2 * NC) + d;
    float x0 = 0.f, x1 = 0.f, x2 = 0.f;
    {
        int lj;
        lj = l0 - 3; if (lj >= 0) x0 = X[(size_t)(dir ? (NL - 1 - lj) : lj) * (2 * NC)];
        lj = l0 - 2; if (lj >= 0) x1 = X[(size_t)(dir ? (NL - 1 - lj) : lj) * (2 * NC)];
        lj = l0 - 1; if (lj >= 0) x2 = X[(size_t)(dir ? (NL - 1 - lj) : lj) * (2 * NC)];
    }
    __nv_bfloat16* oh = g_xch + ((size_t)dg * NL + l0) * NC + d;
    __nv_bfloat16* ol = g_xcl + ((size_t)dg * NL + l0) * NC + d;
    #pragma unroll
    for (int i = 0; i < 8; i++) {
        int l = l0 + i;
        int src = dir ? (NL - 1 - l) : l;
        float x3 = X[(size_t)src * (2 * NC)];
        float s = bias;
        s = fmaf(wv.x, x0, s); s = fmaf(wv.y, x1, s);
        s = fmaf(wv.z, x2, s); s = fmaf(wv.w, x3, s);
        float v = s / (1.0f + __expf(-s));
        __nv_bfloat16 hh, ll;
        bsplit(v, hh, ll);
        oh[(size_t)i * NC] = hh;
        ol[(size_t)i * NC] = ll;
        x0 = x1; x1 = x2; x2 = x3;
    }
}

// ---------------------------------------------------------------------------
// Fused scan (dt_proj + softplus + selective scan)
// ---------------------------------------------------------------------------
__device__ __forceinline__ float softplusf(float s) {
    return (s > 20.0f) ? s : log1pf(__expf(s));
}

__global__ void __launch_bounds__(256) scan_pass1_kernel(const float* __restrict__ Wdt,
                                                         const float* __restrict__ dtb,
                                                         const float* __restrict__ AlogF,
                                                         const float* __restrict__ AlogB) {
    __shared__ float sm[CHUNK * 36];
    const int d  = threadIdx.x;
    const int ck = blockIdx.x;
    const int dg = blockIdx.y;
    const int dir = dg >> 3;
    {
        const float* xd = g_xdbl + ((size_t)dg * NL + ck * CHUNK) * NEDBL;
        #pragma unroll
        for (int it = 0; it < 4; it++) {
            int flat = threadIdx.x + it * 256;
            int row = flat >> 3, c4 = flat & 7;
            float4 v = *reinterpret_cast<const float4*>(xd + (size_t)row * NEDBL + c4 * 4);
            *reinterpret_cast<float4*>(&sm[row * 36 + c4 * 4]) = v;
        }
    }
    __syncthreads();
    const float* Alog = (dir ? AlogB : AlogF) + d * NST;
    float A[NST];
    #pragma unroll
    for (int n = 0; n < NST; n++) A[n] = -__expf(Alog[n]);
    float Wr[NRK];
    #pragma unroll
    for (int q = 0; q < 4; q++) {
        float4 v = *reinterpret_cast<const float4*>(Wdt + d * NRK + q * 4);
        Wr[q * 4] = v.x; Wr[q * 4 + 1] = v.y; Wr[q * 4 + 2] = v.z; Wr[q * 4 + 3] = v.w;
    }
    float bias = dtb[d];
    const __nv_bfloat16* uh = g_xch + ((size_t)dg * NL + ck * CHUNK) * NC + d;
    const __nv_bfloat16* ul = g_xcl + ((size_t)dg * NL + ck * CHUNK) * NC + d;
    float h[NST], ap[NST];
    #pragma unroll
    for (int n = 0; n < NST; n++) { h[n] = 0.0f; ap[n] = 1.0f; }
    for (int t = 0; t < CHUNK; t++) {
        const float* srow = sm + t * 36;
        float s = bias;
        #pragma unroll
        for (int r = 0; r < NRK; r++) s = fmaf(Wr[r], srow[r], s);
        float dl = softplusf(s);
        float u = __bfloat162float(uh[(size_t)t * NC]) + __bfloat162float(ul[(size_t)t * NC]);
        float du = dl * u;
        #pragma unroll
        for (int n = 0; n < NST; n++) {
            float a = __expf(dl * A[n]);
            ap[n] *= a;
            h[n] = fmaf(a, h[n], du * srow[NRK + n]);
        }
    }
    float* apO = g_ap   + (((size_t)dg * NCHUNK + ck) * NST) * NC + d;
    float* heO = g_hend + (((size_t)dg * NCHUNK + ck) * NST) * NC + d;
    #pragma unroll
    for (int n = 0; n < NST; n++) { apO[n * NC] = ap[n]; heO[n * NC] = h[n]; }
}

__global__ void __launch_bounds__(256) scan_combine_kernel() {
    int idx = blockIdx.x * 256 + threadIdx.x;
    int d  = idx & (NC - 1);
    int n  = (idx >> 8) & 7;
    int dg = idx >> 11;
    size_t base = ((size_t)dg * NCHUNK * NST + n) * NC + d;
    float h = 0.0f;
    for (int k = 0; k < NCHUNK; k++) {
        size_t o = base + (size_t)k * NST * NC;
        g_hin[o] = h;
        h = g_ap[o] * h + g_hend[o];
    }
}

// pass2: raw y (incl. D*u), per-direction buffer, no gating
__global__ void __launch_bounds__(256) scan_pass2_kernel(int dir,
                                                         const float* __restrict__ Wdt,
                                                         const float* __restrict__ dtb,
                                                         const float* __restrict__ Alog,
                                                         const float* __restrict__ Dp,
                                                         float* __restrict__ Yout) {
    __shared__ float sm[CHUNK * 36];
    const int d  = threadIdx.x;
    const int ck = blockIdx.x;
    const int g  = blockIdx.y;
    const int dg = dir * NG + g;
    {
        const float* xd = g_xdbl + ((size_t)dg * NL + ck * CHUNK) * NEDBL;
        #pragma unroll
        for (int it = 0; it < 4; it++) {
            int flat = threadIdx.x + it * 256;
            int row = flat >> 3, c4 = flat & 7;
            float4 v = *reinterpret_cast<const float4*>(xd + (size_t)row * NEDBL + c4 * 4);
            *reinterpret_cast<float4*>(&sm[row * 36 + c4 * 4]) = v;
        }
    }
    __syncthreads();
    float A[NST];
    #pragma unroll
    for (int n = 0; n < NST; n++) A[n] = -__expf(Alog[d * NST + n]);
    float Wr[NRK];
    #pragma unroll
    for (int q = 0; q < 4; q++) {
        float4 v = *reinterpret_cast<const float4*>(Wdt + d * NRK + q * 4);
        Wr[q * 4] = v.x; Wr[q * 4 + 1] = v.y; Wr[q * 4 + 2] = v.z; Wr[q * 4 + 3] = v.w;
    }
    float bias = dtb[d];
    float Dd = Dp[d];
    const __nv_bfloat16* uh = g_xch + ((size_t)dg * NL + ck * CHUNK) * NC + d;
    const __nv_bfloat16* ul = g_xcl + ((size_t)dg * NL + ck * CHUNK) * NC + d;
    const float* hiP = g_hin + (((size_t)dg * NCHUNK + ck) * NST) * NC + d;
    float h[NST];
    #pragma unroll
    for (int n = 0; n < NST; n++) h[n] = hiP[n * NC];
    for (int t = 0; t < CHUNK; t++) {
        const float* srow = sm + t * 36;
        float s = bias;
        #pragma unroll
        for (int r = 0; r < NRK; r++) s = fmaf(Wr[r], srow[r], s);
        float dl = softplusf(s);
        float u = __bfloat162float(uh[(size_t)t * NC]) + __bfloat162float(ul[(size_t)t * NC]);
        float du = dl * u;
        float accv = 0.0f;
        #pragma unroll
        for (int n = 0; n < NST; n++) {
            float a = __expf(dl * A[n]);
            h[n] = fmaf(a, h[n], du * srow[NRK + n]);
            accv = fmaf(h[n], srow[NRK + NST + n], accv);
        }
        float yv = fmaf(Dd, u, accv);
        int l  = ck * CHUNK + t;
        int lo = dir ? (NL - 1 - l) : l;
        Yout[((size_t)g * NL + lo) * NC + d] = yv;
    }
}

// ---------------------------------------------------------------------------
// final transpose
// ---------------------------------------------------------------------------
__global__ void __launch_bounds__(256) out_transpose_kernel(float* __restrict__ out) {
    __shared__ float tile[32][33];
    int g  = blockIdx.z;
    int c0 = blockIdx.y * 32;
    int l0 = blockIdx.x * 32;
    int tx = threadIdx.x;
    for (int r = threadIdx.y; r < 32; r += 8)
        tile[r][tx] = g_x[((size_t)g * NL + (l0 + r)) * NC + c0 + tx];
    __syncthreads();
    for (int r = threadIdx.y; r < 32; r += 8)
        out[((size_t)g * NC + (c0 + r)) * NL + l0 + tx] = tile[tx][r];
}

// ---------------------------------------------------------------------------
// Launch
// ---------------------------------------------------------------------------
extern "C" void kernel_launch(void* const* d_in, const int* in_sizes, int n_in,
                              void* d_out, int out_size) {
    const float* data       = (const float*)d_in[0];
    const float* ln_w       = (const float*)d_in[1];
    const float* ln_b       = (const float*)d_in[2];
    const float* in_proj_w  = (const float*)d_in[3];
    const float* conv_w     = (const float*)d_in[4];
    const float* conv_b     = (const float*)d_in[5];
    const float* x_proj_w   = (const float*)d_in[6];
    const float* dt_proj_w  = (const float*)d_in[7];
    const float* dt_proj_b  = (const float*)d_in[8];
    const float* A_log      = (const float*)d_in[9];
    const float* A_b_log    = (const float*)d_in[10];
    const float* Dparam     = (const float*)d_in[11];
    const float* out_proj_w = (const float*)d_in[12];
    const float* mn_w       = (const float*)d_in[13];
    const float* mn_b       = (const float*)d_in[14];
    const int*   record_len = (const int*)d_in[15];
    float* out = (float*)d_out;

    float *d_xz, *d_xdbl, *d_y0, *d_y1, *d_gl;
    cudaGetSymbolAddress((void**)&d_xz,  g_xz);
    cudaGetSymbolAddress((void**)&d_xdbl,g_xdbl);
    cudaGetSymbolAddress((void**)&d_y0,  g_y0);
    cudaGetSymbolAddress((void**)&d_y1,  g_y1);
    cudaGetSymbolAddress((void**)&d_gl,  g_gl);
    __nv_bfloat16 *d_xnh, *d_xnl, *d_xch, *d_xcl;
    __nv_bfloat16 *d_wih, *d_wil, *d_wxh, *d_wxl, *d_woh, *d_wol;
    cudaGetSymbolAddress((void**)&d_xnh, g_xnh);
    cudaGetSymbolAddress((void**)&d_xnl, g_xnl);
    cudaGetSymbolAddress((void**)&d_xch, g_xch);
    cudaGetSymbolAddress((void**)&d_xcl, g_xcl);
    cudaGetSymbolAddress((void**)&d_wih, g_wih);
    cudaGetSymbolAddress((void**)&d_wil, g_wil);
    cudaGetSymbolAddress((void**)&d_wxh, g_wxh);
    cudaGetSymbolAddress((void**)&d_wxl, g_wxl);
    cudaGetSymbolAddress((void**)&d_woh, g_woh);
    cudaGetSymbolAddress((void**)&d_wol, g_wol);

    static bool attrs_set = false;
    if (!attrs_set) {
        cudaFuncSetAttribute(gemm_pre<128>, cudaFuncAttributeMaxDynamicSharedMemorySize, 81920);
        cudaFuncSetAttribute(gemm_pre<32>,  cudaFuncAttributeMaxDynamicSharedMemorySize, 51200);
        attrs_set = true;
    }

    wsplit_kernel<<<(NDEPTH * 512 * NC + 255) / 256, 256>>>(in_proj_w,  d_wih, d_wil, NDEPTH * 512 * NC);
    wsplit_kernel<<<(NDEPTH * NEDBL * NC + 255) / 256, 256>>>(x_proj_w,  d_wxh, d_wxl, NDEPTH * NEDBL * NC);
    wsplit_kernel<<<(NDEPTH * NC * NC + 255) / 256, 256>>>(out_proj_w, d_woh, d_wol, NDEPTH * NC * NC);

    mean_kernel<<<dim3(NL / 32, NC / 32, NG), dim3(32, 8)>>>(data, record_len);
    ln1_kernel<<<NG * NL / 8, 256>>>(ln_w, ln_b);   // layer 0

    for (int i = 0; i < NDEPTH; i++) {
        gemm_pre<128><<<dim3(NL / 128, 4, NG), 256, 81920>>>(
            d_xnh, d_xnl, d_wih + (size_t)i * 512 * NC, d_wil + (size_t)i * 512 * NC, d_xz, 512);
        conv_silu_kernel<<<dim3(NL / 8, 2 * NG), 256>>>(conv_w + i * NC * 4, conv_b + i * NC);
        gemm_pre<32><<<dim3(NL / 128, 1, 2 * NG), 256, 51200>>>(
            d_xch, d_xcl, d_wxh + (size_t)i * NEDBL * NC, d_wxl + (size_t)i * NEDBL * NC, d_xdbl, NEDBL);
        scan_pass1_kernel<<<dim3(NCHUNK, 2 * NG), 256>>>(
            dt_proj_w + (size_t)i * NC * NRK, dt_proj_b + i * NC,
            A_log + (size_t)i * NC * NST, A_b_log + (size_t)i * NC * NST);
        scan_combine_kernel<<<(2 * NG * NST * NC) / 256, 256>>>();
        scan_pass2_kernel<<<dim3(NCHUNK, NG), 256>>>(0,
            dt_proj_w + (size_t)i * NC * NRK, dt_proj_b + i * NC,
            A_log + (size_t)i * NC * NST, Dparam + i * NC, d_y0);
        scan_pass2_kernel<<<dim3(NCHUNK, NG), 256>>>(1,
            dt_proj_w + (size_t)i * NC * NRK, dt_proj_b + i * NC,
            A_b_log + (size_t)i * NC * NST, Dparam + i * NC, d_y1);
        gemm_gated<<<dim3(NL / 128, 2, NG), 256>>>(
            d_y0, d_y1, d_xz, d_woh + (size_t)i * NC * NC, d_wol + (size_t)i * NC * NC, d_gl, 256);
        if (i < NDEPTH - 1)
            ln2ln1_kernel<<<NG * NL / 8, 256>>>(mn_w + i * NC, mn_b + i * NC,
                                                ln_w + (i + 1) * NC, ln_b + (i + 1) * NC);
        else
            ln2_kernel<<<NG * NL / 8, 256>>>(mn_w + i * NC, mn_b + i * NC);
    }

    out_transpose_kernel<<<dim3(NL / 32, NC / 32, NG), dim3(32, 8)>>>(out);
}

// round 7
// speedup vs baseline: 1.0105x; 1.0105x over previous
#include <cuda_runtime.h>
#include <cuda_bf16.h>
#include <math.h>
#include <stdint.h>

// ---------------------------------------------------------------------------
// Problem constants
// ---------------------------------------------------------------------------
#define NG     8
#define NC     256
#define NL     4096
#define NST    8
#define NRK    16
#define NEDBL  32
#define NCHUNK 32
#define CHUNK  128
#define NDEPTH 4

// ---------------------------------------------------------------------------
// Scratch
// ---------------------------------------------------------------------------
__device__ float g_x   [NG * NL * NC];            // residual stream (g,l,c)
__device__ float g_xz  [NG * NL * 2 * NC];        // in_proj out [xx|z]
__device__ float g_xdbl[2 * NG * NL * NEDBL];     // x_proj out (dt|B|C)
__device__ float g_y0  [NG * NL * NC];            // fwd raw scan out
__device__ float g_y1  [NG * NL * NC];            // bwd raw scan out
__device__ float g_gl  [NG * NL * NC];            // out_proj out
__device__ float g_ap  [2 * NG * NCHUNK * NST * NC];
__device__ float g_hend[2 * NG * NCHUNK * NST * NC];
__device__ float g_hin [2 * NG * NCHUNK * NST * NC];
__device__ __nv_bfloat16 g_xnh[NG * NL * NC], g_xnl[NG * NL * NC];    // ln1 split
__device__ __nv_bfloat16 g_xch[2 * NG * NL * NC], g_xcl[2 * NG * NL * NC]; // conv split
__device__ __nv_bfloat16 g_wih[NDEPTH * 512 * NC], g_wil[NDEPTH * 512 * NC];
__device__ __nv_bfloat16 g_wxh[NDEPTH * NEDBL * NC], g_wxl[NDEPTH * NEDBL * NC];
__device__ __nv_bfloat16 g_woh[NDEPTH * NC * NC], g_wol[NDEPTH * NC * NC];

// ---------------------------------------------------------------------------
// Helpers
// ---------------------------------------------------------------------------
__device__ __forceinline__ uint32_t smem_u32(const void* p) {
    uint32_t a;
    asm("{ .reg .u64 t; cvta.to.shared.u64 t, %1; cvt.u32.u64 %0, t; }" : "=r"(a) : "l"(p));
    return a;
}
__device__ __forceinline__ uint32_t pack2(__nv_bfloat16 a, __nv_bfloat16 b) {
    __nv_bfloat162 t(a, b);
    return *reinterpret_cast<uint32_t*>(&t);
}
__device__ __forceinline__ void bsplit(float v, __nv_bfloat16& h, __nv_bfloat16& l) {
    h = __float2bfloat16(v);
    l = __float2bfloat16(v - __bfloat162float(h));
}
__device__ __forceinline__ void cp16(uint32_t dst, const void* src) {
    asm volatile("cp.async.cg.shared.global [%0], [%1], 16;" :: "r"(dst), "l"(src));
}
__device__ __forceinline__ void cp_commit() {
    asm volatile("cp.async.commit_group;" ::: "memory");
}
__device__ __forceinline__ void cp_wait1() {
    asm volatile("cp.async.wait_group 1;" ::: "memory");
}
__device__ __forceinline__ void ldsm_x4(uint32_t& r0, uint32_t& r1, uint32_t& r2,
                                        uint32_t& r3, uint32_t addr) {
    asm volatile("ldmatrix.sync.aligned.m8n8.x4.shared.b16 {%0,%1,%2,%3}, [%4];"
                 : "=r"(r0), "=r"(r1), "=r"(r2), "=r"(r3) : "r"(addr));
}
__device__ __forceinline__ void ldsm_x2(uint32_t& r0, uint32_t& r1, uint32_t addr) {
    asm volatile("ldmatrix.sync.aligned.m8n8.x2.shared.b16 {%0,%1}, [%2];"
                 : "=r"(r0), "=r"(r1) : "r"(addr));
}
__device__ __forceinline__ void mma_bf16(float* d, const uint32_t* a, const uint32_t* b) {
    asm volatile("mma.sync.aligned.m16n8k16.row.col.f32.bf16.bf16.f32 "
                 "{%0,%1,%2,%3}, {%4,%5,%6,%7}, {%8,%9}, {%0,%1,%2,%3};"
                 : "+f"(d[0]), "+f"(d[1]), "+f"(d[2]), "+f"(d[3])
                 : "r"(a[0]), "r"(a[1]), "r"(a[2]), "r"(a[3]), "r"(b[0]), "r"(b[1]));
}

// ---------------------------------------------------------------------------
// Weight split (fp32 -> bf16 hi/lo), once per launch
// ---------------------------------------------------------------------------
__global__ void __launch_bounds__(256) wsplit_kernel(const float* __restrict__ w,
                                                     __nv_bfloat16* __restrict__ h,
                                                     __nv_bfloat16* __restrict__ l, int n) {
    int i = blockIdx.x * 256 + threadIdx.x;
    if (i < n) {
        __nv_bfloat16 hh, ll;
        bsplit(w[i], hh, ll);
        h[i] = hh; l[i] = ll;
    }
}

// ---------------------------------------------------------------------------
// Segment mean + transpose
// ---------------------------------------------------------------------------
__global__ void __launch_bounds__(256) mean_kernel(const float* __restrict__ data,
                                                   const int* __restrict__ rl) {
    __shared__ float tile[32][33];
    int g  = blockIdx.z;
    int c0 = blockIdx.y * 32;
    int l0 = blockIdx.x * 32;
    int start = 0;
    for (int gg = 0; gg < g; gg++) start += rl[gg];
    int cnt = rl[g];
    float inv = 1.0f / (float)cnt;
    int tx = threadIdx.x;
    for (int r = threadIdx.y; r < 32; r += 8) {
        float s = 0.0f;
        for (int a = 0; a < cnt; a++)
            s += data[((size_t)(start + a) * NC + (c0 + r)) * NL + l0 + tx];
        tile[r][tx] = s * inv;
    }
    __syncthreads();
    for (int r = threadIdx.y; r < 32; r += 8)
        g_x[((size_t)g * NL + (l0 + r)) * NC + c0 + tx] = tile[tx][r];
}

// ---------------------------------------------------------------------------
// LayerNorm
// ---------------------------------------------------------------------------
__device__ __forceinline__ void warp_stats8(const float* o, float& mu, float& rstd) {
    float s = 0.f, s2 = 0.f;
    #pragma unroll
    for (int i = 0; i < 8; i++) { s += o[i]; s2 += o[i] * o[i]; }
    #pragma unroll
    for (int off = 16; off; off >>= 1) {
        s  += __shfl_xor_sync(0xffffffffu, s, off);
        s2 += __shfl_xor_sync(0xffffffffu, s2, off);
    }
    mu = s * (1.0f / NC);
    float var = s2 * (1.0f / NC) - mu * mu;
    rstd = rsqrtf(var + 1e-5f);
}

// LN1 standalone (layer 0): g_x -> xnh/xnl
__global__ void __launch_bounds__(256) ln1_kernel(const float* __restrict__ w,
                                                  const float* __restrict__ b) {
    int row  = blockIdx.x * 8 + (threadIdx.x >> 5);
    int lane = threadIdx.x & 31;
    const float* xr = g_x + (size_t)row * NC + lane * 8;
    float v[8];
    *reinterpret_cast<float4*>(&v[0]) = *(const float4*)(xr);
    *reinterpret_cast<float4*>(&v[4]) = *(const float4*)(xr + 4);
    float mu, rstd;
    warp_stats8(v, mu, rstd);
    __nv_bfloat16 hh[8], ll[8];
    #pragma unroll
    for (int i = 0; i < 8; i++) {
        float o = (v[i] - mu) * rstd * w[lane * 8 + i] + b[lane * 8 + i];
        bsplit(o, hh[i], ll[i]);
    }
    uint4 vh = {pack2(hh[0],hh[1]), pack2(hh[2],hh[3]), pack2(hh[4],hh[5]), pack2(hh[6],hh[7])};
    uint4 vl = {pack2(ll[0],ll[1]), pack2(ll[2],ll[3]), pack2(ll[4],ll[5]), pack2(ll[6],ll[7])};
    *reinterpret_cast<uint4*>(g_xnh + (size_t)row * NC + lane * 8) = vh;
    *reinterpret_cast<uint4*>(g_xnl + (size_t)row * NC + lane * 8) = vl;
}

// Fused: LN2(g_gl)+residual -> g_x, then LN1(next layer) -> xnh/xnl
__global__ void __launch_bounds__(256) ln2ln1_kernel(const float* __restrict__ mw,
                                                     const float* __restrict__ mb,
                                                     const float* __restrict__ lw,
                                                     const float* __restrict__ lb) {
    int row  = blockIdx.x * 8 + (threadIdx.x >> 5);
    int lane = threadIdx.x & 31;
    const float* xr = g_gl + (size_t)row * NC + lane * 8;
    float v[8];
    *reinterpret_cast<float4*>(&v[0]) = *(const float4*)(xr);
    *reinterpret_cast<float4*>(&v[4]) = *(const float4*)(xr + 4);
    float mu, rstd;
    warp_stats8(v, mu, rstd);
    float* srow = g_x + (size_t)row * NC + lane * 8;
    float sk[8];
    *reinterpret_cast<float4*>(&sk[0]) = *(const float4*)(srow);
    *reinterpret_cast<float4*>(&sk[4]) = *(const float4*)(srow + 4);
    float nx[8];
    #pragma unroll
    for (int i = 0; i < 8; i++)
        nx[i] = (v[i] - mu) * rstd * mw[lane * 8 + i] + mb[lane * 8 + i] + sk[i];
    *(float4*)(srow)     = *reinterpret_cast<float4*>(&nx[0]);
    *(float4*)(srow + 4) = *reinterpret_cast<float4*>(&nx[4]);
    float mu2, rstd2;
    warp_stats8(nx, mu2, rstd2);
    __nv_bfloat16 hh[8], ll[8];
    #pragma unroll
    for (int i = 0; i < 8; i++) {
        float o = (nx[i] - mu2) * rstd2 * lw[lane * 8 + i] + lb[lane * 8 + i];
        bsplit(o, hh[i], ll[i]);
    }
    uint4 vh = {pack2(hh[0],hh[1]), pack2(hh[2],hh[3]), pack2(hh[4],hh[5]), pack2(hh[6],hh[7])};
    uint4 vl = {pack2(ll[0],ll[1]), pack2(ll[2],ll[3]), pack2(ll[4],ll[5]), pack2(ll[6],ll[7])};
    *reinterpret_cast<uint4*>(g_xnh + (size_t)row * NC + lane * 8) = vh;
    *reinterpret_cast<uint4*>(g_xnl + (size_t)row * NC + lane * 8) = vl;
}

// LN2 plain (last layer)
__global__ void __launch_bounds__(256) ln2_kernel(const float* __restrict__ w,
                                                  const float* __restrict__ b) {
    int row  = blockIdx.x * 8 + (threadIdx.x >> 5);
    int lane = threadIdx.x & 31;
    const float* xr = g_gl + (size_t)row * NC + lane * 8;
    float v[8];
    *reinterpret_cast<float4*>(&v[0]) = *(const float4*)(xr);
    *reinterpret_cast<float4*>(&v[4]) = *(const float4*)(xr + 4);
    float mu, rstd;
    warp_stats8(v, mu, rstd);
    float* srow = g_x + (size_t)row * NC + lane * 8;
    float sk[8];
    *reinterpret_cast<float4*>(&sk[0]) = *(const float4*)(srow);
    *reinterpret_cast<float4*>(&sk[4]) = *(const float4*)(srow + 4);
    float nx[8];
    #pragma unroll
    for (int i = 0; i < 8; i++)
        nx[i] = (v[i] - mu) * rstd * w[lane * 8 + i] + b[lane * 8 + i] + sk[i];
    *(float4*)(srow)     = *reinterpret_cast<float4*>(&nx[0]);
    *(float4*)(srow + 4) = *reinterpret_cast<float4*>(&nx[4]);
}

// ---------------------------------------------------------------------------
// Pipelined HMMA GEMM (pre-split bf16 A): C = A @ W^T, K=256
//   2-stage cp.async double buffer, dynamic smem.
//   Stage layout (pitch 80B rows): Ah[128][40] | Al[128][40] | Bh[NT][40] | Bl[NT][40]
// ---------------------------------------------------------------------------
template<int NT>
__global__ void __launch_bounds__(256) gemm_pre(const __nv_bfloat16* __restrict__ Ah,
                                                const __nv_bfloat16* __restrict__ Al,
                                                const __nv_bfloat16* __restrict__ Wh,
                                                const __nv_bfloat16* __restrict__ Wl,
                                                float* __restrict__ C, int ldc) {
    constexpr int WN   = (NT == 128) ? 32 : 8;
    constexpr int NSUB = WN / 8;
    constexpr int BOFF = 20480;
    constexpr int STG  = 20480 + 2 * NT * 80;
    extern __shared__ char dsm[];
    const uint32_t sb = smem_u32(dsm);

    const int tid = threadIdx.x, wid = tid >> 5, lane = tid & 31;
    const int l0 = blockIdx.x * 128, n0 = blockIdx.y * NT;
    const size_t aoff = (size_t)blockIdx.z * NL * NC;
    const int wm = (wid & 1) * 64;
    const int wn = (wid >> 1) * WN;
    const int arow = tid >> 1, ahalf = tid & 1;

    float acc[4][NSUB][4];
    #pragma unroll
    for (int mi = 0; mi < 4; mi++)
        #pragma unroll
        for (int ni = 0; ni < NSUB; ni++)
            #pragma unroll
            for (int q = 0; q < 4; q++) acc[mi][ni][q] = 0.0f;

    // stage issue: copy k-chunk kci into buffer buf
    auto issue = [&](int kci, int buf) {
        uint32_t base = sb + buf * STG;
        int kc = kci * 32;
        const __nv_bfloat16* ag = Ah + aoff + (size_t)(l0 + arow) * NC + kc + ahalf * 16;
        const __nv_bfloat16* alg = Al + aoff + (size_t)(l0 + arow) * NC + kc + ahalf * 16;
        uint32_t ad = base + arow * 80 + ahalf * 32;
        cp16(ad, ag);            cp16(ad + 16, ag + 8);
        cp16(ad + 10240, alg);   cp16(ad + 10240 + 16, alg + 8);
        if (NT == 128 || tid < NT * 2) {
            int brow = tid >> 1, bhalf = tid & 1;
            const __nv_bfloat16* bg  = Wh + (size_t)(n0 + brow) * NC + kc + bhalf * 16;
            const __nv_bfloat16* blg = Wl + (size_t)(n0 + brow) * NC + kc + bhalf * 16;
            uint32_t bd = base + BOFF + brow * 80 + bhalf * 32;
            cp16(bd, bg);             cp16(bd + 16, bg + 8);
            cp16(bd + NT * 80, blg);  cp16(bd + NT * 80 + 16, blg + 8);
        }
    };

    issue(0, 0);
    cp_commit();

    for (int kci = 0; kci < 8; kci++) {
        int buf = kci & 1;
        if (kci + 1 < 8) issue(kci + 1, buf ^ 1);
        cp_commit();
        cp_wait1();
        __syncthreads();
        uint32_t abase = sb + buf * STG;
        #pragma unroll
        for (int kk = 0; kk < 32; kk += 16) {
            uint32_t ah[4][4], al[4][4];
            #pragma unroll
            for (int mi = 0; mi < 4; mi++) {
                uint32_t ad = abase + (wm + mi * 16 + (lane & 15)) * 80 + (kk + (lane >> 4) * 8) * 2;
                ldsm_x4(ah[mi][0], ah[mi][1], ah[mi][2], ah[mi][3], ad);
                ldsm_x4(al[mi][0], al[mi][1], al[mi][2], al[mi][3], ad + 10240);
            }
            uint32_t bh[NSUB][2], bl[NSUB][2];
            #pragma unroll
            for (int ni = 0; ni < NSUB; ni++) {
                uint32_t bd = abase + BOFF + (wn + ni * 8 + (lane & 7)) * 80 + (kk + ((lane >> 3) & 1) * 8) * 2;
                ldsm_x2(bh[ni][0], bh[ni][1], bd);
                ldsm_x2(bl[ni][0], bl[ni][1], bd + NT * 80);
            }
            #pragma unroll
            for (int mi = 0; mi < 4; mi++)
                #pragma unroll
                for (int ni = 0; ni < NSUB; ni++) {
                    mma_bf16(acc[mi][ni], ah[mi], bh[ni]);
                    mma_bf16(acc[mi][ni], ah[mi], bl[ni]);
                    mma_bf16(acc[mi][ni], al[mi], bh[ni]);
                }
        }
        __syncthreads();
    }
    float* Cg = C + (size_t)blockIdx.z * NL * ldc;
    #pragma unroll
    for (int mi = 0; mi < 4; mi++)
        #pragma unroll
        for (int ni = 0; ni < NSUB; ni++) {
            int r = l0 + wm + mi * 16 + (lane >> 2);
            int c = n0 + wn + ni * 8 + (lane & 3) * 2;
            float2 v0 = {acc[mi][ni][0], acc[mi][ni][1]};
            float2 v1 = {acc[mi][ni][2], acc[mi][ni][3]};
            *reinterpret_cast<float2*>(Cg + (size_t)r * ldc + c)       = v0;
            *reinterpret_cast<float2*>(Cg + (size_t)(r + 8) * ldc + c) = v1;
        }
}

// ---------------------------------------------------------------------------
// out_proj GEMM with fused gating: A = 0.5*(y0+y1)*silu(z), split in-kernel.
// ---------------------------------------------------------------------------
__global__ void __launch_bounds__(256) gemm_gated(const float* __restrict__ Y0,
                                                  const float* __restrict__ Y1,
                                                  const float* __restrict__ XZ,
                                                  const __nv_bfloat16* __restrict__ Wh,
                                                  const __nv_bfloat16* __restrict__ Wl,
                                                  float* __restrict__ C, int ldc) {
    __shared__ __nv_bfloat16 Ah_s[128][40];
    __shared__ __nv_bfloat16 Al_s[128][40];
    __shared__ __nv_bfloat16 Bh_s[128][40];
    __shared__ __nv_bfloat16 Bl_s[128][40];

    const int tid = threadIdx.x, wid = tid >> 5, lane = tid & 31;
    const int l0 = blockIdx.x * 128, n0 = blockIdx.y * 128, g = blockIdx.z;
    const int wm = (wid & 1) * 64;
    const int wn = (wid >> 1) * 32;
    const int arow = tid >> 1, ahalf = tid & 1;

    float acc[4][4][4];
    #pragma unroll
    for (int mi = 0; mi < 4; mi++)
        #pragma unroll
        for (int ni = 0; ni < 4; ni++)
            #pragma unroll
            for (int q = 0; q < 4; q++) acc[mi][ni][q] = 0.0f;

    for (int kc = 0; kc < NC; kc += 32) {
        // stage A: gated y
        {
            const float* y0 = Y0 + (size_t)g * NL * NC + (size_t)(l0 + arow) * NC + kc + ahalf * 16;
            const float* y1 = Y1 + (size_t)g * NL * NC + (size_t)(l0 + arow) * NC + kc + ahalf * 16;
            const float* zp = XZ + (size_t)g * NL * 512 + (size_t)(l0 + arow) * 512 + 256 + kc + ahalf * 16;
            float f[16];
            #pragma unroll
            for (int q = 0; q < 4; q++) {
                float4 a0 = *reinterpret_cast<const float4*>(y0 + q * 4);
                float4 a1 = *reinterpret_cast<const float4*>(y1 + q * 4);
                float4 zz = *reinterpret_cast<const float4*>(zp + q * 4);
                f[q*4+0] = 0.5f * (a0.x + a1.x) * (zz.x / (1.0f + __expf(-zz.x)));
                f[q*4+1] = 0.5f * (a0.y + a1.y) * (zz.y / (1.0f + __expf(-zz.y)));
                f[q*4+2] = 0.5f * (a0.z + a1.z) * (zz.z / (1.0f + __expf(-zz.z)));
                f[q*4+3] = 0.5f * (a0.w + a1.w) * (zz.w / (1.0f + __expf(-zz.w)));
            }
            __nv_bfloat16 hh[16], ll[16];
            #pragma unroll
            for (int j = 0; j < 16; j++) bsplit(f[j], hh[j], ll[j]);
            uint4 vh0 = {pack2(hh[0],hh[1]),  pack2(hh[2],hh[3]),  pack2(hh[4],hh[5]),  pack2(hh[6],hh[7])};
            uint4 vh1 = {pack2(hh[8],hh[9]),  pack2(hh[10],hh[11]),pack2(hh[12],hh[13]),pack2(hh[14],hh[15])};
            uint4 vl0 = {pack2(ll[0],ll[1]),  pack2(ll[2],ll[3]),  pack2(ll[4],ll[5]),  pack2(ll[6],ll[7])};
            uint4 vl1 = {pack2(ll[8],ll[9]),  pack2(ll[10],ll[11]),pack2(ll[12],ll[13]),pack2(ll[14],ll[15])};
            *reinterpret_cast<uint4*>(&Ah_s[arow][ahalf * 16])     = vh0;
            *reinterpret_cast<uint4*>(&Ah_s[arow][ahalf * 16 + 8]) = vh1;
            *reinterpret_cast<uint4*>(&Al_s[arow][ahalf * 16])     = vl0;
            *reinterpret_cast<uint4*>(&Al_s[arow][ahalf * 16 + 8]) = vl1;
        }
        // stage B
        {
            const __nv_bfloat16* bg  = Wh + (size_t)(n0 + arow) * NC + kc + ahalf * 16;
            const __nv_bfloat16* blg = Wl + (size_t)(n0 + arow) * NC + kc + ahalf * 16;
            uint4 h0 = *reinterpret_cast<const uint4*>(bg);
            uint4 h1 = *reinterpret_cast<const uint4*>(bg + 8);
            uint4 l0v = *reinterpret_cast<const uint4*>(blg);
            uint4 l1v = *reinterpret_cast<const uint4*>(blg + 8);
            *reinterpret_cast<uint4*>(&Bh_s[arow][ahalf * 16])     = h0;
            *reinterpret_cast<uint4*>(&Bh_s[arow][ahalf * 16 + 8]) = h1;
            *reinterpret_cast<uint4*>(&Bl_s[arow][ahalf * 16])     = l0v;
            *reinterpret_cast<uint4*>(&Bl_s[arow][ahalf * 16 + 8]) = l1v;
        }
        __syncthreads();
        #pragma unroll
        for (int kk = 0; kk < 32; kk += 16) {
            uint32_t ah[4][4], al[4][4];
            #pragma unroll
            for (int mi = 0; mi < 4; mi++) {
                uint32_t ad = smem_u32(&Ah_s[wm + mi * 16 + (lane & 15)][kk + (lane >> 4) * 8]);
                ldsm_x4(ah[mi][0], ah[mi][1], ah[mi][2], ah[mi][3], ad);
                ad = smem_u32(&Al_s[wm + mi * 16 + (lane & 15)][kk + (lane >> 4) * 8]);
                ldsm_x4(al[mi][0], al[mi][1], al[mi][2], al[mi][3], ad);
            }
            uint32_t bh[4][2], bl[4][2];
            #pragma unroll
            for (int ni = 0; ni < 4; ni++) {
                uint32_t bd = smem_u32(&Bh_s[wn + ni * 8 + (lane & 7)][kk + ((lane >> 3) & 1) * 8]);
                ldsm_x2(bh[ni][0], bh[ni][1], bd);
                bd = smem_u32(&Bl_s[wn + ni * 8 + (lane & 7)][kk + ((lane >> 3) & 1) * 8]);
                ldsm_x2(bl[ni][0], bl[ni][1], bd);
            }
            #pragma unroll
            for (int mi = 0; mi < 4; mi++)
                #pragma unroll
                for (int ni = 0; ni < 4; ni++) {
                    mma_bf16(acc[mi][ni], ah[mi], bh[ni]);
                    mma_bf16(acc[mi][ni], ah[mi], bl[ni]);
                    mma_bf16(acc[mi][ni], al[mi], bh[ni]);
                }
        }
        __syncthreads();
    }
    float* Cg = C + (size_t)g * NL * ldc;
    #pragma unroll
    for (int mi = 0; mi < 4; mi++)
        #pragma unroll
        for (int ni = 0; ni < 4; ni++) {
            int r = l0 + wm + mi * 16 + (lane >> 2);
            int c = n0 + wn + ni * 8 + (lane & 3) * 2;
            float2 v0 = {acc[mi][ni][0], acc[mi][ni][1]};
            float2 v1 = {acc[mi][ni][2], acc[mi][ni][3]};
            *reinterpret_cast<float2*>(Cg + (size_t)r * ldc + c)       = v0;
            *reinterpret_cast<float2*>(Cg + (size_t)(r + 8) * ldc + c) = v1;
        }
}

// ---------------------------------------------------------------------------
// conv(k=4 causal) + SiLU -> bf16 hi/lo pair
// ---------------------------------------------------------------------------
__global__ void __launch_bounds__(256) conv_silu_kernel(const float* __restrict__ cw,
                                                        const float* __restrict__ cb) {
    int d  = threadIdx.x;
    int l0 = blockIdx.x * 8;
    int dg = blockIdx.y;
    int dir = dg >> 3, g = dg & 7;
    float4 wv = *reinterpret_cast<const float4*>(cw + d * 4);
    float bias = cb[d];
    const float* X = g_xz + (size_t)g * NL * (2 * NC) + d;
    float x0 = 0.f, x1 = 0.f, x2 = 0.f;
    {
        int lj;
        lj = l0 - 3; if (lj >= 0) x0 = X[(size_t)(dir ? (NL - 1 - lj) : lj) * (2 * NC)];
        lj = l0 - 2; if (lj >= 0) x1 = X[(size_t)(dir ? (NL - 1 - lj) : lj) * (2 * NC)];
        lj = l0 - 1; if (lj >= 0) x2 = X[(size_t)(dir ? (NL - 1 - lj) : lj) * (2 * NC)];
    }
    __nv_bfloat16* oh = g_xch + ((size_t)dg * NL + l0) * NC + d;
    __nv_bfloat16* ol = g_xcl + ((size_t)dg * NL + l0) * NC + d;
    #pragma unroll
    for (int i = 0; i < 8; i++) {
        int l = l0 + i;
        int src = dir ? (NL - 1 - l) : l;
        float x3 = X[(size_t)src * (2 * NC)];
        float s = bias;
        s = fmaf(wv.x, x0, s); s = fmaf(wv.y, x1, s);
        s = fmaf(wv.z, x2, s); s = fmaf(wv.w, x3, s);
        float v = s / (1.0f + __expf(-s));
        __nv_bfloat16 hh, ll;
        bsplit(v, hh, ll);
        oh[(size_t)i * NC] = hh;
        ol[(size_t)i * NC] = ll;
        x0 = x1; x1 = x2; x2 = x3;
    }
}

// ---------------------------------------------------------------------------
// Fused scan (dt_proj + softplus + selective scan)
// ---------------------------------------------------------------------------
__device__ __forceinline__ float softplusf(float s) {
    return (s > 20.0f) ? s : log1pf(__expf(s));
}

__global__ void __launch_bounds__(256) scan_pass1_kernel(const float* __restrict__ Wdt,
                                                         const float* __restrict__ dtb,
                                                         const float* __restrict__ AlogF,
                                                         const float* __restrict__ AlogB) {
    __shared__ float sm[CHUNK * 36];
    const int d  = threadIdx.x;
    const int ck = blockIdx.x;
    const int dg = blockIdx.y;
    const int dir = dg >> 3;
    {
        const float* xd = g_xdbl + ((size_t)dg * NL + ck * CHUNK) * NEDBL;
        #pragma unroll
        for (int it = 0; it < 4; it++) {
            int flat = threadIdx.x + it * 256;
            int row = flat >> 3, c4 = flat & 7;
            float4 v = *reinterpret_cast<const float4*>(xd + (size_t)row * NEDBL + c4 * 4);
            *reinterpret_cast<float4*>(&sm[row * 36 + c4 * 4]) = v;
        }
    }
    __syncthreads();
    const float* Alog = (dir ? AlogB : AlogF) + d * NST;
    float A[NST];
    #pragma unroll
    for (int n = 0; n < NST; n++) A[n] = -__expf(Alog[n]);
    float Wr[NRK];
    #pragma unroll
    for (int q = 0; q < 4; q++) {
        float4 v = *reinterpret_cast<const float4*>(Wdt + d * NRK + q * 4);
        Wr[q * 4] = v.x; Wr[q * 4 + 1] = v.y; Wr[q * 4 + 2] = v.z; Wr[q * 4 + 3] = v.w;
    }
    float bias = dtb[d];
    const __nv_bfloat16* uh = g_xch + ((size_t)dg * NL + ck * CHUNK) * NC + d;
    const __nv_bfloat16* ul = g_xcl + ((size_t)dg * NL + ck * CHUNK) * NC + d;
    float h[NST], ap[NST];
    #pragma unroll
    for (int n = 0; n < NST; n++) { h[n] = 0.0f; ap[n] = 1.0f; }
    for (int t = 0; t < CHUNK; t++) {
        const float* srow = sm + t * 36;
        float s = bias;
        #pragma unroll
        for (int r = 0; r < NRK; r++) s = fmaf(Wr[r], srow[r], s);
        float dl = softplusf(s);
        float u = __bfloat162float(uh[(size_t)t * NC]) + __bfloat162float(ul[(size_t)t * NC]);
        float du = dl * u;
        #pragma unroll
        for (int n = 0; n < NST; n++) {
            float a = __expf(dl * A[n]);
            ap[n] *= a;
            h[n] = fmaf(a, h[n], du * srow[NRK + n]);
        }
    }
    float* apO = g_ap   + (((size_t)dg * NCHUNK + ck) * NST) * NC + d;
    float* heO = g_hend + (((size_t)dg * NCHUNK + ck) * NST) * NC + d;
    #pragma unroll
    for (int n = 0; n < NST; n++) { apO[n * NC] = ap[n]; heO[n * NC] = h[n]; }
}

__global__ void __launch_bounds__(256) scan_combine_kernel() {
    int idx = blockIdx.x * 256 + threadIdx.x;
    int d  = idx & (NC - 1);
    int n  = (idx >> 8) & 7;
    int dg = idx >> 11;
    size_t base = ((size_t)dg * NCHUNK * NST + n) * NC + d;
    float h = 0.0f;
    for (int k = 0; k < NCHUNK; k++) {
        size_t o = base + (size_t)k * NST * NC;
        g_hin[o] = h;
        h = g_ap[o] * h + g_hend[o];
    }
}

// pass2: raw y (incl. D*u), per-direction buffer, no gating
__global__ void __launch_bounds__(256) scan_pass2_kernel(int dir,
                                                         const float* __restrict__ Wdt,
                                                         const float* __restrict__ dtb,
                                                         const float* __restrict__ Alog,
                                                         const float* __restrict__ Dp,
                                                         float* __restrict__ Yout) {
    __shared__ float sm[CHUNK * 36];
    const int d  = threadIdx.x;
    const int ck = blockIdx.x;
    const int g  = blockIdx.y;
    const int dg = dir * NG + g;
    {
        const float* xd = g_xdbl + ((size_t)dg * NL + ck * CHUNK) * NEDBL;
        #pragma unroll
        for (int it = 0; it < 4; it++) {
            int flat = threadIdx.x + it * 256;
            int row = flat >> 3, c4 = flat & 7;
            float4 v = *reinterpret_cast<const float4*>(xd + (size_t)row * NEDBL + c4 * 4);
            *reinterpret_cast<float4*>(&sm[row * 36 + c4 * 4]) = v;
        }
    }
    __syncthreads();
    float A[NST];
    #pragma unroll
    for (int n = 0; n < NST; n++) A[n] = -__expf(Alog[d * NST + n]);
    float Wr[NRK];
    #pragma unroll
    for (int q = 0; q < 4; q++) {
        float4 v = *reinterpret_cast<const float4*>(Wdt + d * NRK + q * 4);
        Wr[q * 4] = v.x; Wr[q * 4 + 1] = v.y; Wr[q * 4 + 2] = v.z; Wr[q * 4 + 3] = v.w;
    }
    float bias = dtb[d];
    float Dd = Dp[d];
    const __nv_bfloat16* uh = g_xch + ((size_t)dg * NL + ck * CHUNK) * NC + d;
    const __nv_bfloat16* ul = g_xcl + ((size_t)dg * NL + ck * CHUNK) * NC + d;
    const float* hiP = g_hin + (((size_t)dg * NCHUNK + ck) * NST) * NC + d;
    float h[NST];
    #pragma unroll
    for (int n = 0; n < NST; n++) h[n] = hiP[n * NC];
    for (int t = 0; t < CHUNK; t++) {
        const float* srow = sm + t * 36;
        float s = bias;
        #pragma unroll
        for (int r = 0; r < NRK; r++) s = fmaf(Wr[r], srow[r], s);
        float dl = softplusf(s);
        float u = __bfloat162float(uh[(size_t)t * NC]) + __bfloat162float(ul[(size_t)t * NC]);
        float du = dl * u;
        float accv = 0.0f;
        #pragma unroll
        for (int n = 0; n < NST; n++) {
            float a = __expf(dl * A[n]);
            h[n] = fmaf(a, h[n], du * srow[NRK + n]);
            accv = fmaf(h[n], srow[NRK + NST + n], accv);
        }
        float yv = fmaf(Dd, u, accv);
        int l  = ck * CHUNK + t;
        int lo = dir ? (NL - 1 - l) : l;
        Yout[((size_t)g * NL + lo) * NC + d] = yv;
    }
}

// ---------------------------------------------------------------------------
// final transpose
// ---------------------------------------------------------------------------
__global__ void __launch_bounds__(256) out_transpose_kernel(float* __restrict__ out) {
    __shared__ float tile[32][33];
    int g  = blockIdx.z;
    int c0 = blockIdx.y * 32;
    int l0 = blockIdx.x * 32;
    int tx = threadIdx.x;
    for (int r = threadIdx.y; r < 32; r += 8)
        tile[r][tx] = g_x[((size_t)g * NL + (l0 + r)) * NC + c0 + tx];
    __syncthreads();
    for (int r = threadIdx.y; r < 32; r += 8)
        out[((size_t)g * NC + (c0 + r)) * NL + l0 + tx] = tile[tx][r];
}

// ---------------------------------------------------------------------------
// Launch
// ---------------------------------------------------------------------------
extern "C" void kernel_launch(void* const* d_in, const int* in_sizes, int n_in,
                              void* d_out, int out_size) {
    const float* data       = (const float*)d_in[0];
    const float* ln_w       = (const float*)d_in[1];
    const float* ln_b       = (const float*)d_in[2];
    const float* in_proj_w  = (const float*)d_in[3];
    const float* conv_w     = (const float*)d_in[4];
    const float* conv_b     = (const float*)d_in[5];
    const float* x_proj_w   = (const float*)d_in[6];
    const float* dt_proj_w  = (const float*)d_in[7];
    const float* dt_proj_b  = (const float*)d_in[8];
    const float* A_log      = (const float*)d_in[9];
    const float* A_b_log    = (const float*)d_in[10];
    const float* Dparam     = (const float*)d_in[11];
    const float* out_proj_w = (const float*)d_in[12];
    const float* mn_w       = (const float*)d_in[13];
    const float* mn_b       = (const float*)d_in[14];
    const int*   record_len = (const int*)d_in[15];
    float* out = (float*)d_out;

    float *d_xz, *d_xdbl, *d_y0, *d_y1, *d_gl;
    cudaGetSymbolAddress((void**)&d_xz,  g_xz);
    cudaGetSymbolAddress((void**)&d_xdbl,g_xdbl);
    cudaGetSymbolAddress((void**)&d_y0,  g_y0);
    cudaGetSymbolAddress((void**)&d_y1,  g_y1);
    cudaGetSymbolAddress((void**)&d_gl,  g_gl);
    __nv_bfloat16 *d_xnh, *d_xnl, *d_xch, *d_xcl;
    __nv_bfloat16 *d_wih, *d_wil, *d_wxh, *d_wxl, *d_woh, *d_wol;
    cudaGetSymbolAddress((void**)&d_xnh, g_xnh);
    cudaGetSymbolAddress((void**)&d_xnl, g_xnl);
    cudaGetSymbolAddress((void**)&d_xch, g_xch);
    cudaGetSymbolAddress((void**)&d_xcl, g_xcl);
    cudaGetSymbolAddress((void**)&d_wih, g_wih);
    cudaGetSymbolAddress((void**)&d_wil, g_wil);
    cudaGetSymbolAddress((void**)&d_wxh, g_wxh);
    cudaGetSymbolAddress((void**)&d_wxl, g_wxl);
    cudaGetSymbolAddress((void**)&d_woh, g_woh);
    cudaGetSymbolAddress((void**)&d_wol, g_wol);

    static bool attrs_set = false;
    if (!attrs_set) {
        cudaFuncSetAttribute(gemm_pre<128>, cudaFuncAttributeMaxDynamicSharedMemorySize, 81920);
        cudaFuncSetAttribute(gemm_pre<32>,  cudaFuncAttributeMaxDynamicSharedMemorySize, 51200);
        attrs_set = true;
    }

    wsplit_kernel<<<(NDEPTH * 512 * NC + 255) / 256, 256>>>(in_proj_w,  d_wih, d_wil, NDEPTH * 512 * NC);
    wsplit_kernel<<<(NDEPTH * NEDBL * NC + 255) / 256, 256>>>(x_proj_w,  d_wxh, d_wxl, NDEPTH * NEDBL * NC);
    wsplit_kernel<<<(NDEPTH * NC * NC + 255) / 256, 256>>>(out_proj_w, d_woh, d_wol, NDEPTH * NC * NC);

    mean_kernel<<<dim3(NL / 32, NC / 32, NG), dim3(32, 8)>>>(data, record_len);
    ln1_kernel<<<NG * NL / 8, 256>>>(ln_w, ln_b);   // layer 0

    for (int i = 0; i < NDEPTH; i++) {
        gemm_pre<128><<<dim3(NL / 128, 4, NG), 256, 81920>>>(
            d_xnh, d_xnl, d_wih + (size_t)i * 512 * NC, d_wil + (size_t)i * 512 * NC, d_xz, 512);
        conv_silu_kernel<<<dim3(NL / 8, 2 * NG), 256>>>(conv_w + i * NC * 4, conv_b + i * NC);
        gemm_pre<32><<<dim3(NL / 128, 1, 2 * NG), 256, 51200>>>(
            d_xch, d_xcl, d_wxh + (size_t)i * NEDBL * NC, d_wxl + (size_t)i * NEDBL * NC, d_xdbl, NEDBL);
        scan_pass1_kernel<<<dim3(NCHUNK, 2 * NG), 256>>>(
            dt_proj_w + (size_t)i * NC * NRK, dt_proj_b + i * NC,
            A_log + (size_t)i * NC * NST, A_b_log + (size_t)i * NC * NST);
        scan_combine_kernel<<<(2 * NG * NST * NC) / 256, 256>>>();
        scan_pass2_kernel<<<dim3(NCHUNK, NG), 256>>>(0,
            dt_proj_w + (size_t)i * NC * NRK, dt_proj_b + i * NC,
            A_log + (size_t)i * NC * NST, Dparam + i * NC, d_y0);
        scan_pass2_kernel<<<dim3(NCHUNK, NG), 256>>>(1,
            dt_proj_w + (size_t)i * NC * NRK, dt_proj_b + i * NC,
            A_b_log + (size_t)i * NC * NST, Dparam + i * NC, d_y1);
        gemm_gated<<<dim3(NL / 128, 2, NG), 256>>>(
            d_y0, d_y1, d_xz, d_woh + (size_t)i * NC * NC, d_wol + (size_t)i * NC * NC, d_gl, 256);
        if (i < NDEPTH - 1)
            ln2ln1_kernel<<<NG * NL / 8, 256>>>(mn_w + i * NC, mn_b + i * NC,
                                                ln_w + (i + 1) * NC, ln_b + (i + 1) * NC);
        else
            ln2_kernel<<<NG * NL / 8, 256>>>(mn_w + i * NC, mn_b + i * NC);
    }

    out_transpose_kernel<<<dim3(NL / 32, NC / 32, NG), dim3(32, 8)>>>(out);
}

// round 8
// speedup vs baseline: 1.0174x; 1.0068x over previous
#include <cuda_runtime.h>
#include <cuda_bf16.h>
#include <math.h>
#include <stdint.h>

// ---------------------------------------------------------------------------
// Problem constants
// ---------------------------------------------------------------------------
#define NG     8
#define NC     256
#define NL     4096
#define NST    8
#define NRK    16
#define NEDBL  32
#define NCHUNK 32
#define CHUNK  128
#define NDEPTH 4

// ---------------------------------------------------------------------------
// Scratch
// ---------------------------------------------------------------------------
__device__ float g_x   [NG * NL * NC];            // residual stream (g,l,c)
__device__ float g_xz  [NG * NL * 2 * NC];        // in_proj out [xx|z]
__device__ float g_xdbl[2 * NG * NL * NEDBL];     // x_proj out (dt|B|C)
__device__ float g_y0  [NG * NL * NC];            // fwd raw scan out
__device__ float g_y1  [NG * NL * NC];            // bwd raw scan out
__device__ float g_gl  [NG * NL * NC];            // out_proj out
__device__ float g_ap  [2 * NG * NCHUNK * NST * NC];
__device__ float g_hend[2 * NG * NCHUNK * NST * NC];
__device__ float g_hin [2 * NG * NCHUNK * NST * NC];
__device__ __nv_bfloat16 g_xnh[NG * NL * NC], g_xnl[NG * NL * NC];    // ln1 split
__device__ __nv_bfloat16 g_xch[2 * NG * NL * NC], g_xcl[2 * NG * NL * NC]; // conv split
__device__ __nv_bfloat16 g_wih[NDEPTH * 512 * NC], g_wil[NDEPTH * 512 * NC];
__device__ __nv_bfloat16 g_wxh[NDEPTH * NEDBL * NC], g_wxl[NDEPTH * NEDBL * NC];
__device__ __nv_bfloat16 g_woh[NDEPTH * NC * NC], g_wol[NDEPTH * NC * NC];

// ---------------------------------------------------------------------------
// Helpers
// ---------------------------------------------------------------------------
__device__ __forceinline__ uint32_t smem_u32(const void* p) {
    uint32_t a;
    asm("{ .reg .u64 t; cvta.to.shared.u64 t, %1; cvt.u32.u64 %0, t; }" : "=r"(a) : "l"(p));
    return a;
}
__device__ __forceinline__ uint32_t pack2(__nv_bfloat16 a, __nv_bfloat16 b) {
    __nv_bfloat162 t(a, b);
    return *reinterpret_cast<uint32_t*>(&t);
}
__device__ __forceinline__ void bsplit(float v, __nv_bfloat16& h, __nv_bfloat16& l) {
    h = __float2bfloat16(v);
    l = __float2bfloat16(v - __bfloat162float(h));
}
__device__ __forceinline__ void cp16(uint32_t dst, const void* src) {
    asm volatile("cp.async.cg.shared.global [%0], [%1], 16;" :: "r"(dst), "l"(src));
}
__device__ __forceinline__ void cp_commit() {
    asm volatile("cp.async.commit_group;" ::: "memory");
}
__device__ __forceinline__ void cp_wait1() {
    asm volatile("cp.async.wait_group 1;" ::: "memory");
}
__device__ __forceinline__ void ldsm_x4(uint32_t& r0, uint32_t& r1, uint32_t& r2,
                                        uint32_t& r3, uint32_t addr) {
    asm volatile("ldmatrix.sync.aligned.m8n8.x4.shared.b16 {%0,%1,%2,%3}, [%4];"
                 : "=r"(r0), "=r"(r1), "=r"(r2), "=r"(r3) : "r"(addr));
}
__device__ __forceinline__ void ldsm_x2(uint32_t& r0, uint32_t& r1, uint32_t addr) {
    asm volatile("ldmatrix.sync.aligned.m8n8.x2.shared.b16 {%0,%1}, [%2];"
                 : "=r"(r0), "=r"(r1) : "r"(addr));
}
__device__ __forceinline__ void mma_bf16(float* d, const uint32_t* a, const uint32_t* b) {
    asm volatile("mma.sync.aligned.m16n8k16.row.col.f32.bf16.bf16.f32 "
                 "{%0,%1,%2,%3}, {%4,%5,%6,%7}, {%8,%9}, {%0,%1,%2,%3};"
                 : "+f"(d[0]), "+f"(d[1]), "+f"(d[2]), "+f"(d[3])
                 : "r"(a[0]), "r"(a[1]), "r"(a[2]), "r"(a[3]), "r"(b[0]), "r"(b[1]));
}

// ---------------------------------------------------------------------------
// Weight split (fp32 -> bf16 hi/lo), once per launch
// ---------------------------------------------------------------------------
__global__ void __launch_bounds__(256) wsplit_kernel(const float* __restrict__ w,
                                                     __nv_bfloat16* __restrict__ h,
                                                     __nv_bfloat16* __restrict__ l, int n) {
    int i = blockIdx.x * 256 + threadIdx.x;
    if (i < n) {
        __nv_bfloat16 hh, ll;
        bsplit(w[i], hh, ll);
        h[i] = hh; l[i] = ll;
    }
}

// ---------------------------------------------------------------------------
// Segment mean + transpose
// ---------------------------------------------------------------------------
__global__ void __launch_bounds__(256) mean_kernel(const float* __restrict__ data,
                                                   const int* __restrict__ rl) {
    __shared__ float tile[32][33];
    int g  = blockIdx.z;
    int c0 = blockIdx.y * 32;
    int l0 = blockIdx.x * 32;
    int start = 0;
    for (int gg = 0; gg < g; gg++) start += rl[gg];
    int cnt = rl[g];
    float inv = 1.0f / (float)cnt;
    int tx = threadIdx.x;
    for (int r = threadIdx.y; r < 32; r += 8) {
        float s = 0.0f;
        for (int a = 0; a < cnt; a++)
            s += data[((size_t)(start + a) * NC + (c0 + r)) * NL + l0 + tx];
        tile[r][tx] = s * inv;
    }
    __syncthreads();
    for (int r = threadIdx.y; r < 32; r += 8)
        g_x[((size_t)g * NL + (l0 + r)) * NC + c0 + tx] = tile[tx][r];
}

// ---------------------------------------------------------------------------
// LayerNorm
// ---------------------------------------------------------------------------
__device__ __forceinline__ void warp_stats8(const float* o, float& mu, float& rstd) {
    float s = 0.f, s2 = 0.f;
    #pragma unroll
    for (int i = 0; i < 8; i++) { s += o[i]; s2 += o[i] * o[i]; }
    #pragma unroll
    for (int off = 16; off; off >>= 1) {
        s  += __shfl_xor_sync(0xffffffffu, s, off);
        s2 += __shfl_xor_sync(0xffffffffu, s2, off);
    }
    mu = s * (1.0f / NC);
    float var = s2 * (1.0f / NC) - mu * mu;
    rstd = rsqrtf(var + 1e-5f);
}

// LN1 standalone (layer 0): g_x -> xnh/xnl
__global__ void __launch_bounds__(256) ln1_kernel(const float* __restrict__ w,
                                                  const float* __restrict__ b) {
    int row  = blockIdx.x * 8 + (threadIdx.x >> 5);
    int lane = threadIdx.x & 31;
    const float* xr = g_x + (size_t)row * NC + lane * 8;
    float v[8];
    *reinterpret_cast<float4*>(&v[0]) = *(const float4*)(xr);
    *reinterpret_cast<float4*>(&v[4]) = *(const float4*)(xr + 4);
    float mu, rstd;
    warp_stats8(v, mu, rstd);
    __nv_bfloat16 hh[8], ll[8];
    #pragma unroll
    for (int i = 0; i < 8; i++) {
        float o = (v[i] - mu) * rstd * w[lane * 8 + i] + b[lane * 8 + i];
        bsplit(o, hh[i], ll[i]);
    }
    uint4 vh = {pack2(hh[0],hh[1]), pack2(hh[2],hh[3]), pack2(hh[4],hh[5]), pack2(hh[6],hh[7])};
    uint4 vl = {pack2(ll[0],ll[1]), pack2(ll[2],ll[3]), pack2(ll[4],ll[5]), pack2(ll[6],ll[7])};
    *reinterpret_cast<uint4*>(g_xnh + (size_t)row * NC + lane * 8) = vh;
    *reinterpret_cast<uint4*>(g_xnl + (size_t)row * NC + lane * 8) = vl;
}

// Fused: LN2(g_gl)+residual -> g_x, then LN1(next layer) -> xnh/xnl
__global__ void __launch_bounds__(256) ln2ln1_kernel(const float* __restrict__ mw,
                                                     const float* __restrict__ mb,
                                                     const float* __restrict__ lw,
                                                     const float* __restrict__ lb) {
    int row  = blockIdx.x * 8 + (threadIdx.x >> 5);
    int lane = threadIdx.x & 31;
    const float* xr = g_gl + (size_t)row * NC + lane * 8;
    float v[8];
    *reinterpret_cast<float4*>(&v[0]) = *(const float4*)(xr);
    *reinterpret_cast<float4*>(&v[4]) = *(const float4*)(xr + 4);
    float mu, rstd;
    warp_stats8(v, mu, rstd);
    float* srow = g_x + (size_t)row * NC + lane * 8;
    float sk[8];
    *reinterpret_cast<float4*>(&sk[0]) = *(const float4*)(srow);
    *reinterpret_cast<float4*>(&sk[4]) = *(const float4*)(srow + 4);
    float nx[8];
    #pragma unroll
    for (int i = 0; i < 8; i++)
        nx[i] = (v[i] - mu) * rstd * mw[lane * 8 + i] + mb[lane * 8 + i] + sk[i];
    *(float4*)(srow)     = *reinterpret_cast<float4*>(&nx[0]);
    *(float4*)(srow + 4) = *reinterpret_cast<float4*>(&nx[4]);
    float mu2, rstd2;
    warp_stats8(nx, mu2, rstd2);
    __nv_bfloat16 hh[8], ll[8];
    #pragma unroll
    for (int i = 0; i < 8; i++) {
        float o = (nx[i] - mu2) * rstd2 * lw[lane * 8 + i] + lb[lane * 8 + i];
        bsplit(o, hh[i], ll[i]);
    }
    uint4 vh = {pack2(hh[0],hh[1]), pack2(hh[2],hh[3]), pack2(hh[4],hh[5]), pack2(hh[6],hh[7])};
    uint4 vl = {pack2(ll[0],ll[1]), pack2(ll[2],ll[3]), pack2(ll[4],ll[5]), pack2(ll[6],ll[7])};
    *reinterpret_cast<uint4*>(g_xnh + (size_t)row * NC + lane * 8) = vh;
    *reinterpret_cast<uint4*>(g_xnl + (size_t)row * NC + lane * 8) = vl;
}

// LN2 plain (last layer)
__global__ void __launch_bounds__(256) ln2_kernel(const float* __restrict__ w,
                                                  const float* __restrict__ b) {
    int row  = blockIdx.x * 8 + (threadIdx.x >> 5);
    int lane = threadIdx.x & 31;
    const float* xr = g_gl + (size_t)row * NC + lane * 8;
    float v[8];
    *reinterpret_cast<float4*>(&v[0]) = *(const float4*)(xr);
    *reinterpret_cast<float4*>(&v[4]) = *(const float4*)(xr + 4);
    float mu, rstd;
    warp_stats8(v, mu, rstd);
    float* srow = g_x + (size_t)row * NC + lane * 8;
    float sk[8];
    *reinterpret_cast<float4*>(&sk[0]) = *(const float4*)(srow);
    *reinterpret_cast<float4*>(&sk[4]) = *(const float4*)(srow + 4);
    float nx[8];
    #pragma unroll
    for (int i = 0; i < 8; i++)
        nx[i] = (v[i] - mu) * rstd * w[lane * 8 + i] + b[lane * 8 + i] + sk[i];
    *(float4*)(srow)     = *reinterpret_cast<float4*>(&nx[0]);
    *(float4*)(srow + 4) = *reinterpret_cast<float4*>(&nx[4]);
}

// ---------------------------------------------------------------------------
// Pipelined HMMA GEMM (pre-split bf16 A): C = A @ W^T, K=256
//   2-stage cp.async double buffer, dynamic smem.
//   Stage layout (pitch 80B rows): Ah[128][40] | Al[128][40] | Bh[NT][40] | Bl[NT][40]
// ---------------------------------------------------------------------------
template<int NT>
__global__ void __launch_bounds__(256) gemm_pre(const __nv_bfloat16* __restrict__ Ah,
                                                const __nv_bfloat16* __restrict__ Al,
                                                const __nv_bfloat16* __restrict__ Wh,
                                                const __nv_bfloat16* __restrict__ Wl,
                                                float* __restrict__ C, int ldc) {
    constexpr int WN   = (NT == 128) ? 32 : 8;
    constexpr int NSUB = WN / 8;
    constexpr int BOFF = 20480;
    constexpr int STG  = 20480 + 2 * NT * 80;
    extern __shared__ char dsm[];
    const uint32_t sb = smem_u32(dsm);

    const int tid = threadIdx.x, wid = tid >> 5, lane = tid & 31;
    const int l0 = blockIdx.x * 128, n0 = blockIdx.y * NT;
    const size_t aoff = (size_t)blockIdx.z * NL * NC;
    const int wm = (wid & 1) * 64;
    const int wn = (wid >> 1) * WN;
    const int arow = tid >> 1, ahalf = tid & 1;

    float acc[4][NSUB][4];
    #pragma unroll
    for (int mi = 0; mi < 4; mi++)
        #pragma unroll
        for (int ni = 0; ni < NSUB; ni++)
            #pragma unroll
            for (int q = 0; q < 4; q++) acc[mi][ni][q] = 0.0f;

    // stage issue: copy k-chunk kci into buffer buf
    auto issue = [&](int kci, int buf) {
        uint32_t base = sb + buf * STG;
        int kc = kci * 32;
        const __nv_bfloat16* ag = Ah + aoff + (size_t)(l0 + arow) * NC + kc + ahalf * 16;
        const __nv_bfloat16* alg = Al + aoff + (size_t)(l0 + arow) * NC + kc + ahalf * 16;
        uint32_t ad = base + arow * 80 + ahalf * 32;
        cp16(ad, ag);            cp16(ad + 16, ag + 8);
        cp16(ad + 10240, alg);   cp16(ad + 10240 + 16, alg + 8);
        if (NT == 128 || tid < NT * 2) {
            int brow = tid >> 1, bhalf = tid & 1;
            const __nv_bfloat16* bg  = Wh + (size_t)(n0 + brow) * NC + kc + bhalf * 16;
            const __nv_bfloat16* blg = Wl + (size_t)(n0 + brow) * NC + kc + bhalf * 16;
            uint32_t bd = base + BOFF + brow * 80 + bhalf * 32;
            cp16(bd, bg);             cp16(bd + 16, bg + 8);
            cp16(bd + NT * 80, blg);  cp16(bd + NT * 80 + 16, blg + 8);
        }
    };

    issue(0, 0);
    cp_commit();

    for (int kci = 0; kci < 8; kci++) {
        int buf = kci & 1;
        if (kci + 1 < 8) issue(kci + 1, buf ^ 1);
        cp_commit();
        cp_wait1();
        __syncthreads();
        uint32_t abase = sb + buf * STG;
        #pragma unroll
        for (int kk = 0; kk < 32; kk += 16) {
            uint32_t ah[4][4], al[4][4];
            #pragma unroll
            for (int mi = 0; mi < 4; mi++) {
                uint32_t ad = abase + (wm + mi * 16 + (lane & 15)) * 80 + (kk + (lane >> 4) * 8) * 2;
                ldsm_x4(ah[mi][0], ah[mi][1], ah[mi][2], ah[mi][3], ad);
                ldsm_x4(al[mi][0], al[mi][1], al[mi][2], al[mi][3], ad + 10240);
            }
            uint32_t bh[NSUB][2], bl[NSUB][2];
            #pragma unroll
            for (int ni = 0; ni < NSUB; ni++) {
                uint32_t bd = abase + BOFF + (wn + ni * 8 + (lane & 7)) * 80 + (kk + ((lane >> 3) & 1) * 8) * 2;
                ldsm_x2(bh[ni][0], bh[ni][1], bd);
                ldsm_x2(bl[ni][0], bl[ni][1], bd + NT * 80);
            }
            #pragma unroll
            for (int mi = 0; mi < 4; mi++)
                #pragma unroll
                for (int ni = 0; ni < NSUB; ni++) {
                    mma_bf16(acc[mi][ni], ah[mi], bh[ni]);
                    mma_bf16(acc[mi][ni], ah[mi], bl[ni]);
                    mma_bf16(acc[mi][ni], al[mi], bh[ni]);
                }
        }
        __syncthreads();
    }
    float* Cg = C + (size_t)blockIdx.z * NL * ldc;
    #pragma unroll
    for (int mi = 0; mi < 4; mi++)
        #pragma unroll
        for (int ni = 0; ni < NSUB; ni++) {
            int r = l0 + wm + mi * 16 + (lane >> 2);
            int c = n0 + wn + ni * 8 + (lane & 3) * 2;
            float2 v0 = {acc[mi][ni][0], acc[mi][ni][1]};
            float2 v1 = {acc[mi][ni][2], acc[mi][ni][3]};
            *reinterpret_cast<float2*>(Cg + (size_t)r * ldc + c)       = v0;
            *reinterpret_cast<float2*>(Cg + (size_t)(r + 8) * ldc + c) = v1;
        }
}

// ---------------------------------------------------------------------------
// out_proj GEMM with fused gating: A = 0.5*(y0+y1)*silu(z), split in-kernel.
// ---------------------------------------------------------------------------
__global__ void __launch_bounds__(256) gemm_gated(const float* __restrict__ Y0,
                                                  const float* __restrict__ Y1,
                                                  const float* __restrict__ XZ,
                                                  const __nv_bfloat16* __restrict__ Wh,
                                                  const __nv_bfloat16* __restrict__ Wl,
                                                  float* __restrict__ C, int ldc) {
    __shared__ __nv_bfloat16 Ah_s[128][40];
    __shared__ __nv_bfloat16 Al_s[128][40];
    __shared__ __nv_bfloat16 Bh_s[128][40];
    __shared__ __nv_bfloat16 Bl_s[128][40];

    const int tid = threadIdx.x, wid = tid >> 5, lane = tid & 31;
    const int l0 = blockIdx.x * 128, n0 = blockIdx.y * 128, g = blockIdx.z;
    const int wm = (wid & 1) * 64;
    const int wn = (wid >> 1) * 32;
    const int arow = tid >> 1, ahalf = tid & 1;

    float acc[4][4][4];
    #pragma unroll
    for (int mi = 0; mi < 4; mi++)
        #pragma unroll
        for (int ni = 0; ni < 4; ni++)
            #pragma unroll
            for (int q = 0; q < 4; q++) acc[mi][ni][q] = 0.0f;

    for (int kc = 0; kc < NC; kc += 32) {
        // stage A: gated y
        {
            const float* y0 = Y0 + (size_t)g * NL * NC + (size_t)(l0 + arow) * NC + kc + ahalf * 16;
            const float* y1 = Y1 + (size_t)g * NL * NC + (size_t)(l0 + arow) * NC + kc + ahalf * 16;
            const float* zp = XZ + (size_t)g * NL * 512 + (size_t)(l0 + arow) * 512 + 256 + kc + ahalf * 16;
            float f[16];
            #pragma unroll
            for (int q = 0; q < 4; q++) {
                float4 a0 = *reinterpret_cast<const float4*>(y0 + q * 4);
                float4 a1 = *reinterpret_cast<const float4*>(y1 + q * 4);
                float4 zz = *reinterpret_cast<const float4*>(zp + q * 4);
                f[q*4+0] = 0.5f * (a0.x + a1.x) * (zz.x / (1.0f + __expf(-zz.x)));
                f[q*4+1] = 0.5f * (a0.y + a1.y) * (zz.y / (1.0f + __expf(-zz.y)));
                f[q*4+2] = 0.5f * (a0.z + a1.z) * (zz.z / (1.0f + __expf(-zz.z)));
                f[q*4+3] = 0.5f * (a0.w + a1.w) * (zz.w / (1.0f + __expf(-zz.w)));
            }
            __nv_bfloat16 hh[16], ll[16];
            #pragma unroll
            for (int j = 0; j < 16; j++) bsplit(f[j], hh[j], ll[j]);
            uint4 vh0 = {pack2(hh[0],hh[1]),  pack2(hh[2],hh[3]),  pack2(hh[4],hh[5]),  pack2(hh[6],hh[7])};
            uint4 vh1 = {pack2(hh[8],hh[9]),  pack2(hh[10],hh[11]),pack2(hh[12],hh[13]),pack2(hh[14],hh[15])};
            uint4 vl0 = {pack2(ll[0],ll[1]),  pack2(ll[2],ll[3]),  pack2(ll[4],ll[5]),  pack2(ll[6],ll[7])};
            uint4 vl1 = {pack2(ll[8],ll[9]),  pack2(ll[10],ll[11]),pack2(ll[12],ll[13]),pack2(ll[14],ll[15])};
            *reinterpret_cast<uint4*>(&Ah_s[arow][ahalf * 16])     = vh0;
            *reinterpret_cast<uint4*>(&Ah_s[arow][ahalf * 16 + 8]) = vh1;
            *reinterpret_cast<uint4*>(&Al_s[arow][ahalf * 16])     = vl0;
            *reinterpret_cast<uint4*>(&Al_s[arow][ahalf * 16 + 8]) = vl1;
        }
        // stage B
        {
            const __nv_bfloat16* bg  = Wh + (size_t)(n0 + arow) * NC + kc + ahalf * 16;
            const __nv_bfloat16* blg = Wl + (size_t)(n0 + arow) * NC + kc + ahalf * 16;
            uint4 h0 = *reinterpret_cast<const uint4*>(bg);
            uint4 h1 = *reinterpret_cast<const uint4*>(bg + 8);
            uint4 l0v = *reinterpret_cast<const uint4*>(blg);
            uint4 l1v = *reinterpret_cast<const uint4*>(blg + 8);
            *reinterpret_cast<uint4*>(&Bh_s[arow][ahalf * 16])     = h0;
            *reinterpret_cast<uint4*>(&Bh_s[arow][ahalf * 16 + 8]) = h1;
            *reinterpret_cast<uint4*>(&Bl_s[arow][ahalf * 16])     = l0v;
            *reinterpret_cast<uint4*>(&Bl_s[arow][ahalf * 16 + 8]) = l1v;
        }
        __syncthreads();
        #pragma unroll
        for (int kk = 0; kk < 32; kk += 16) {
            uint32_t ah[4][4], al[4][4];
            #pragma unroll
            for (int mi = 0; mi < 4; mi++) {
                uint32_t ad = smem_u32(&Ah_s[wm + mi * 16 + (lane & 15)][kk + (lane >> 4) * 8]);
                ldsm_x4(ah[mi][0], ah[mi][1], ah[mi][2], ah[mi][3], ad);
                ad = smem_u32(&Al_s[wm + mi * 16 + (lane & 15)][kk + (lane >> 4) * 8]);
                ldsm_x4(al[mi][0], al[mi][1], al[mi][2], al[mi][3], ad);
            }
            uint32_t bh[4][2], bl[4][2];
            #pragma unroll
            for (int ni = 0; ni < 4; ni++) {
                uint32_t bd = smem_u32(&Bh_s[wn + ni * 8 + (lane & 7)][kk + ((lane >> 3) & 1) * 8]);
                ldsm_x2(bh[ni][0], bh[ni][1], bd);
                bd = smem_u32(&Bl_s[wn + ni * 8 + (lane & 7)][kk + ((lane >> 3) & 1) * 8]);
                ldsm_x2(bl[ni][0], bl[ni][1], bd);
            }
            #pragma unroll
            for (int mi = 0; mi < 4; mi++)
                #pragma unroll
                for (int ni = 0; ni < 4; ni++) {
                    mma_bf16(acc[mi][ni], ah[mi], bh[ni]);
                    mma_bf16(acc[mi][ni], ah[mi], bl[ni]);
                    mma_bf16(acc[mi][ni], al[mi], bh[ni]);
                }
        }
        __syncthreads();
    }
    float* Cg = C + (size_t)g * NL * ldc;
    #pragma unroll
    for (int mi = 0; mi < 4; mi++)
        #pragma unroll
        for (int ni = 0; ni < 4; ni++) {
            int r = l0 + wm + mi * 16 + (lane >> 2);
            int c = n0 + wn + ni * 8 + (lane & 3) * 2;
            float2 v0 = {acc[mi][ni][0], acc[mi][ni][1]};
            float2 v1 = {acc[mi][ni][2], acc[mi][ni][3]};
            *reinterpret_cast<float2*>(Cg + (size_t)r * ldc + c)       = v0;
            *reinterpret_cast<float2*>(Cg + (size_t)(r + 8) * ldc + c) = v1;
        }
}

// ---------------------------------------------------------------------------
// conv(k=4 causal) + SiLU -> bf16 hi/lo pair
// ---------------------------------------------------------------------------
__global__ void __launch_bounds__(256) conv_silu_kernel(const float* __restrict__ cw,
                                                        const float* __restrict__ cb) {
    int d  = threadIdx.x;
    int l0 = blockIdx.x * 8;
    int dg = blockIdx.y;
    int dir = dg >> 3, g = dg & 7;
    float4 wv = *reinterpret_cast<const float4*>(cw + d * 4);
    float bias = cb[d];
    const float* X = g_xz + (size_t)g * NL * (2 * NC) + d;
    float x0 = 0.f, x1 = 0.f, x2 = 0.f;
    {
        int lj;
        lj = l0 - 3; if (lj >= 0) x0 = X[(size_t)(dir ? (NL - 1 - lj) : lj) * (2 * NC)];
        lj = l0 - 2; if (lj >= 0) x1 = X[(size_t)(dir ? (NL - 1 - lj) : lj) * (2 * NC)];
        lj = l0 - 1; if (lj >= 0) x2 = X[(size_t)(dir ? (NL - 1 - lj) : lj) * (2 * NC)];
    }
    __nv_bfloat16* oh = g_xch + ((size_t)dg * NL + l0) * NC + d;
    __nv_bfloat16* ol = g_xcl + ((size_t)dg * NL + l0) * NC + d;
    #pragma unroll
    for (int i = 0; i < 8; i++) {
        int l = l0 + i;
        int src = dir ? (NL - 1 - l) : l;
        float x3 = X[(size_t)src * (2 * NC)];
        float s = bias;
        s = fmaf(wv.x, x0, s); s = fmaf(wv.y, x1, s);
        s = fmaf(wv.z, x2, s); s = fmaf(wv.w, x3, s);
        float v = s / (1.0f + __expf(-s));
        __nv_bfloat16 hh, ll;
        bsplit(v, hh, ll);
        oh[(size_t)i * NC] = hh;
        ol[(size_t)i * NC] = ll;
        x0 = x1; x1 = x2; x2 = x3;
    }
}

// ---------------------------------------------------------------------------
// Fused scan (dt_proj + softplus + selective scan)
// ---------------------------------------------------------------------------
__device__ __forceinline__ float softplusf(float s) {
    return (s > 20.0f) ? s : log1pf(__expf(s));
}

__global__ void __launch_bounds__(256) scan_pass1_kernel(const float* __restrict__ Wdt,
                                                         const float* __restrict__ dtb,
                                                         const float* __restrict__ AlogF,
                                                         const float* __restrict__ AlogB) {
    __shared__ float sm[CHUNK * 36];
    const int d  = threadIdx.x;
    const int ck = blockIdx.x;
    const int dg = blockIdx.y;
    const int dir = dg >> 3;
    {
        const float* xd = g_xdbl + ((size_t)dg * NL + ck * CHUNK) * NEDBL;
        #pragma unroll
        for (int it = 0; it < 4; it++) {
            int flat = threadIdx.x + it * 256;
            int row = flat >> 3, c4 = flat & 7;
            float4 v = *reinterpret_cast<const float4*>(xd + (size_t)row * NEDBL + c4 * 4);
            *reinterpret_cast<float4*>(&sm[row * 36 + c4 * 4]) = v;
        }
    }
    __syncthreads();
    const float* Alog = (dir ? AlogB : AlogF) + d * NST;
    float A[NST];
    #pragma unroll
    for (int n = 0; n < NST; n++) A[n] = -__expf(Alog[n]);
    float Wr[NRK];
    #pragma unroll
    for (int q = 0; q < 4; q++) {
        float4 v = *reinterpret_cast<const float4*>(Wdt + d * NRK + q * 4);
        Wr[q * 4] = v.x; Wr[q * 4 + 1] = v.y; Wr[q * 4 + 2] = v.z; Wr[q * 4 + 3] = v.w;
    }
    float bias = dtb[d];
    const __nv_bfloat16* uh = g_xch + ((size_t)dg * NL + ck * CHUNK) * NC + d;
    const __nv_bfloat16* ul = g_xcl + ((size_t)dg * NL + ck * CHUNK) * NC + d;
    float h[NST], ap[NST];
    #pragma unroll
    for (int n = 0; n < NST; n++) { h[n] = 0.0f; ap[n] = 1.0f; }
    for (int t = 0; t < CHUNK; t++) {
        const float* srow = sm + t * 36;
        float s = bias;
        #pragma unroll
        for (int r = 0; r < NRK; r++) s = fmaf(Wr[r], srow[r], s);
        float dl = softplusf(s);
        float u = __bfloat162float(uh[(size_t)t * NC]) + __bfloat162float(ul[(size_t)t * NC]);
        float du = dl * u;
        #pragma unroll
        for (int n = 0; n < NST; n++) {
            float a = __expf(dl * A[n]);
            ap[n] *= a;
            h[n] = fmaf(a, h[n], du * srow[NRK + n]);
        }
    }
    float* apO = g_ap   + (((size_t)dg * NCHUNK + ck) * NST) * NC + d;
    float* heO = g_hend + (((size_t)dg * NCHUNK + ck) * NST) * NC + d;
    #pragma unroll
    for (int n = 0; n < NST; n++) { apO[n * NC] = ap[n]; heO[n * NC] = h[n]; }
}

__global__ void __launch_bounds__(256) scan_combine_kernel() {
    int idx = blockIdx.x * 256 + threadIdx.x;
    int d  = idx & (NC - 1);
    int n  = (idx >> 8) & 7;
    int dg = idx >> 11;
    size_t base = ((size_t)dg * NCHUNK * NST + n) * NC + d;
    float h = 0.0f;
    for (int k = 0; k < NCHUNK; k++) {
        size_t o = base + (size_t)k * NST * NC;
        g_hin[o] = h;
        h = g_ap[o] * h + g_hend[o];
    }
}

// pass2: raw y (incl. D*u), per-direction buffer, no gating
__global__ void __launch_bounds__(256) scan_pass2_kernel(int dir,
                                                         const float* __restrict__ Wdt,
                                                         const float* __restrict__ dtb,
                                                         const float* __restrict__ Alog,
                                                         const float* __restrict__ Dp,
                                                         float* __restrict__ Yout) {
    __shared__ float sm[CHUNK * 36];
    const int d  = threadIdx.x;
    const int ck = blockIdx.x;
    const int g  = blockIdx.y;
    const int dg = dir * NG + g;
    {
        const float* xd = g_xdbl + ((size_t)dg * NL + ck * CHUNK) * NEDBL;
        #pragma unroll
        for (int it = 0; it < 4; it++) {
            int flat = threadIdx.x + it * 256;
            int row = flat >> 3, c4 = flat & 7;
            float4 v = *reinterpret_cast<const float4*>(xd + (size_t)row * NEDBL + c4 * 4);
            *reinterpret_cast<float4*>(&sm[row * 36 + c4 * 4]) = v;
        }
    }
    __syncthreads();
    float A[NST];
    #pragma unroll
    for (int n = 0; n < NST; n++) A[n] = -__expf(Alog[d * NST + n]);
    float Wr[NRK];
    #pragma unroll
    for (int q = 0; q < 4; q++) {
        float4 v = *reinterpret_cast<const float4*>(Wdt + d * NRK + q * 4);
        Wr[q * 4] = v.x; Wr[q * 4 + 1] = v.y; Wr[q * 4 + 2] = v.z; Wr[q * 4 + 3] = v.w;
    }
    float bias = dtb[d];
    float Dd = Dp[d];
    const __nv_bfloat16* uh = g_xch + ((size_t)dg * NL + ck * CHUNK) * NC + d;
    const __nv_bfloat16* ul = g_xcl + ((size_t)dg * NL + ck * CHUNK) * NC + d;
    const float* hiP = g_hin + (((size_t)dg * NCHUNK + ck) * NST) * NC + d;
    float h[NST];
    #pragma unroll
    for (int n = 0; n < NST; n++) h[n] = hiP[n * NC];
    for (int t = 0; t < CHUNK; t++) {
        const float* srow = sm + t * 36;
        float s = bias;
        #pragma unroll
        for (int r = 0; r < NRK; r++) s = fmaf(Wr[r], srow[r], s);
        float dl = softplusf(s);
        float u = __bfloat162float(uh[(size_t)t * NC]) + __bfloat162float(ul[(size_t)t * NC]);
        float du = dl * u;
        float accv = 0.0f;
        #pragma unroll
        for (int n = 0; n < NST; n++) {
            float a = __expf(dl * A[n]);
            h[n] = fmaf(a, h[n], du * srow[NRK + n]);
            accv = fmaf(h[n], srow[NRK + NST + n], accv);
        }
        float yv = fmaf(Dd, u, accv);
        int l  = ck * CHUNK + t;
        int lo = dir ? (NL - 1 - l) : l;
        Yout[((size_t)g * NL + lo) * NC + d] = yv;
    }
}

// ---------------------------------------------------------------------------
// final transpose
// ---------------------------------------------------------------------------
__global__ void __launch_bounds__(256) out_transpose_kernel(float* __restrict__ out) {
    __shared__ float tile[32][33];
    int g  = blockIdx.z;
    int c0 = blockIdx.y * 32;
    int l0 = blockIdx.x * 32;
    int tx = threadIdx.x;
    for (int r = threadIdx.y; r < 32; r += 8)
        tile[r][tx] = g_x[((size_t)g * NL + (l0 + r)) * NC + c0 + tx];
    __syncthreads();
    for (int r = threadIdx.y; r < 32; r += 8)
        out[((size_t)g * NC + (c0 + r)) * NL + l0 + tx] = tile[tx][r];
}

// ---------------------------------------------------------------------------
// Launch
// ---------------------------------------------------------------------------
extern "C" void kernel_launch(void* const* d_in, const int* in_sizes, int n_in,
                              void* d_out, int out_size) {
    const float* data       = (const float*)d_in[0];
    const float* ln_w       = (const float*)d_in[1];
    const float* ln_b       = (const float*)d_in[2];
    const float* in_proj_w  = (const float*)d_in[3];
    const float* conv_w     = (const float*)d_in[4];
    const float* conv_b     = (const float*)d_in[5];
    const float* x_proj_w   = (const float*)d_in[6];
    const float* dt_proj_w  = (const float*)d_in[7];
    const float* dt_proj_b  = (const float*)d_in[8];
    const float* A_log      = (const float*)d_in[9];
    const float* A_b_log    = (const float*)d_in[10];
    const float* Dparam     = (const float*)d_in[11];
    const float* out_proj_w = (const float*)d_in[12];
    const float* mn_w       = (const float*)d_in[13];
    const float* mn_b       = (const float*)d_in[14];
    const int*   record_len = (const int*)d_in[15];
    float* out = (float*)d_out;

    float *d_xz, *d_xdbl, *d_y0, *d_y1, *d_gl;
    cudaGetSymbolAddress((void**)&d_xz,  g_xz);
    cudaGetSymbolAddress((void**)&d_xdbl,g_xdbl);
    cudaGetSymbolAddress((void**)&d_y0,  g_y0);
    cudaGetSymbolAddress((void**)&d_y1,  g_y1);
    cudaGetSymbolAddress((void**)&d_gl,  g_gl);
    __nv_bfloat16 *d_xnh, *d_xnl, *d_xch, *d_xcl;
    __nv_bfloat16 *d_wih, *d_wil, *d_wxh, *d_wxl, *d_woh, *d_wol;
    cudaGetSymbolAddress((void**)&d_xnh, g_xnh);
    cudaGetSymbolAddress((void**)&d_xnl, g_xnl);
    cudaGetSymbolAddress((void**)&d_xch, g_xch);
    cudaGetSymbolAddress((void**)&d_xcl, g_xcl);
    cudaGetSymbolAddress((void**)&d_wih, g_wih);
    cudaGetSymbolAddress((void**)&d_wil, g_wil);
    cudaGetSymbolAddress((void**)&d_wxh, g_wxh);
    cudaGetSymbolAddress((void**)&d_wxl, g_wxl);
    cudaGetSymbolAddress((void**)&d_woh, g_woh);
    cudaGetSymbolAddress((void**)&d_wol, g_wol);

    static bool attrs_set = false;
    if (!attrs_set) {
        cudaFuncSetAttribute(gemm_pre<128>, cudaFuncAttributeMaxDynamicSharedMemorySize, 81920);
        cudaFuncSetAttribute(gemm_pre<32>,  cudaFuncAttributeMaxDynamicSharedMemorySize, 51200);
        attrs_set = true;
    }

    wsplit_kernel<<<(NDEPTH * 512 * NC + 255) / 256, 256>>>(in_proj_w,  d_wih, d_wil, NDEPTH * 512 * NC);
    wsplit_kernel<<<(NDEPTH * NEDBL * NC + 255) / 256, 256>>>(x_proj_w,  d_wxh, d_wxl, NDEPTH * NEDBL * NC);
    wsplit_kernel<<<(NDEPTH * NC * NC + 255) / 256, 256>>>(out_proj_w, d_woh, d_wol, NDEPTH * NC * NC);

    mean_kernel<<<dim3(NL / 32, NC / 32, NG), dim3(32, 8)>>>(data, record_len);
    ln1_kernel<<<NG * NL / 8, 256>>>(ln_w, ln_b);   // layer 0

    for (int i = 0; i < NDEPTH; i++) {
        gemm_pre<128><<<dim3(NL / 128, 4, NG), 256, 81920>>>(
            d_xnh, d_xnl, d_wih + (size_t)i * 512 * NC, d_wil + (size_t)i * 512 * NC, d_xz, 512);
        conv_silu_kernel<<<dim3(NL / 8, 2 * NG), 256>>>(conv_w + i * NC * 4, conv_b + i * NC);
        gemm_pre<32><<<dim3(NL / 128, 1, 2 * NG), 256, 51200>>>(
            d_xch, d_xcl, d_wxh + (size_t)i * NEDBL * NC, d_wxl + (size_t)i * NEDBL * NC, d_xdbl, NEDBL);
        scan_pass1_kernel<<<dim3(NCHUNK, 2 * NG), 256>>>(
            dt_proj_w + (size_t)i * NC * NRK, dt_proj_b + i * NC,
            A_log + (size_t)i * NC * NST, A_b_log + (size_t)i * NC * NST);
        scan_combine_kernel<<<(2 * NG * NST * NC) / 256, 256>>>();
        scan_pass2_kernel<<<dim3(NCHUNK, NG), 256>>>(0,
            dt_proj_w + (size_t)i * NC * NRK, dt_proj_b + i * NC,
            A_log + (size_t)i * NC * NST, Dparam + i * NC, d_y0);
        scan_pass2_kernel<<<dim3(NCHUNK, NG), 256>>>(1,
            dt_proj_w + (size_t)i * NC * NRK, dt_proj_b + i * NC,
            A_b_log + (size_t)i * NC * NST, Dparam + i * NC, d_y1);
        gemm_gated<<<dim3(NL / 128, 2, NG), 256>>>(
            d_y0, d_y1, d_xz, d_woh + (size_t)i * NC * NC, d_wol + (size_t)i * NC * NC, d_gl, 256);
        if (i < NDEPTH - 1)
            ln2ln1_kernel<<<NG * NL / 8, 256>>>(mn_w + i * NC, mn_b + i * NC,
                                                ln_w + (i + 1) * NC, ln_b + (i + 1) * NC);
        else
            ln2_kernel<<<NG * NL / 8, 256>>>(mn_w + i * NC, mn_b + i * NC);
    }

    out_transpose_kernel<<<dim3(NL / 32, NC / 32, NG), dim3(32, 8)>>>(out);
}

// round 9
// speedup vs baseline: 1.0239x; 1.0064x over previous
#include <cuda_runtime.h>
#include <cuda_bf16.h>
#include <math.h>
#include <stdint.h>

// ---------------------------------------------------------------------------
// Problem constants
// ---------------------------------------------------------------------------
#define NG     8
#define NC     256
#define NL     4096
#define NST    8
#define NRK    16
#define NEDBL  32
#define NCHUNK 32
#define CHUNK  128
#define NDEPTH 4

// ---------------------------------------------------------------------------
// Scratch
// ---------------------------------------------------------------------------
__device__ float g_x   [NG * NL * NC];            // residual stream (g,l,c)
__device__ float g_xz  [NG * NL * 2 * NC];        // in_proj out [xx|z]
__device__ float g_xdbl[2 * NG * NL * NEDBL];     // x_proj out (dt|B|C)
__device__ float g_y0  [NG * NL * NC];            // fwd raw scan out
__device__ float g_y1  [NG * NL * NC];            // bwd raw scan out
__device__ float g_gl  [NG * NL * NC];            // out_proj out
__device__ float g_ap  [2 * NG * NCHUNK * NST * NC];
__device__ float g_hend[2 * NG * NCHUNK * NST * NC];
__device__ float g_hin [2 * NG * NCHUNK * NST * NC];
__device__ __nv_bfloat16 g_xnh[NG * NL * NC], g_xnl[NG * NL * NC];    // ln1 split
__device__ __nv_bfloat16 g_xch[2 * NG * NL * NC], g_xcl[2 * NG * NL * NC]; // conv split
__device__ __nv_bfloat16 g_wih[NDEPTH * 512 * NC], g_wil[NDEPTH * 512 * NC];
__device__ __nv_bfloat16 g_wxh[NDEPTH * NEDBL * NC], g_wxl[NDEPTH * NEDBL * NC];
__device__ __nv_bfloat16 g_woh[NDEPTH * NC * NC], g_wol[NDEPTH * NC * NC];

// ---------------------------------------------------------------------------
// Helpers
// ---------------------------------------------------------------------------
__device__ __forceinline__ uint32_t smem_u32(const void* p) {
    uint32_t a;
    asm("{ .reg .u64 t; cvta.to.shared.u64 t, %1; cvt.u32.u64 %0, t; }" : "=r"(a) : "l"(p));
    return a;
}
__device__ __forceinline__ uint32_t pack2(__nv_bfloat16 a, __nv_bfloat16 b) {
    __nv_bfloat162 t(a, b);
    return *reinterpret_cast<uint32_t*>(&t);
}
__device__ __forceinline__ void bsplit(float v, __nv_bfloat16& h, __nv_bfloat16& l) {
    h = __float2bfloat16(v);
    l = __float2bfloat16(v - __bfloat162float(h));
}
__device__ __forceinline__ void cp16(uint32_t dst, const void* src) {
    asm volatile("cp.async.cg.shared.global [%0], [%1], 16;" :: "r"(dst), "l"(src));
}
__device__ __forceinline__ void cp_commit() {
    asm volatile("cp.async.commit_group;" ::: "memory");
}
__device__ __forceinline__ void cp_wait1() {
    asm volatile("cp.async.wait_group 1;" ::: "memory");
}
__device__ __forceinline__ void ldsm_x4(uint32_t& r0, uint32_t& r1, uint32_t& r2,
                                        uint32_t& r3, uint32_t addr) {
    asm volatile("ldmatrix.sync.aligned.m8n8.x4.shared.b16 {%0,%1,%2,%3}, [%4];"
                 : "=r"(r0), "=r"(r1), "=r"(r2), "=r"(r3) : "r"(addr));
}
__device__ __forceinline__ void ldsm_x2(uint32_t& r0, uint32_t& r1, uint32_t addr) {
    asm volatile("ldmatrix.sync.aligned.m8n8.x2.shared.b16 {%0,%1}, [%2];"
                 : "=r"(r0), "=r"(r1) : "r"(addr));
}
__device__ __forceinline__ void mma_bf16(float* d, const uint32_t* a, const uint32_t* b) {
    asm volatile("mma.sync.aligned.m16n8k16.row.col.f32.bf16.bf16.f32 "
                 "{%0,%1,%2,%3}, {%4,%5,%6,%7}, {%8,%9}, {%0,%1,%2,%3};"
                 : "+f"(d[0]), "+f"(d[1]), "+f"(d[2]), "+f"(d[3])
                 : "r"(a[0]), "r"(a[1]), "r"(a[2]), "r"(a[3]), "r"(b[0]), "r"(b[1]));
}

// ---------------------------------------------------------------------------
// Weight split (fp32 -> bf16 hi/lo), once per launch
// ---------------------------------------------------------------------------
__global__ void __launch_bounds__(256) wsplit_kernel(const float* __restrict__ w,
                                                     __nv_bfloat16* __restrict__ h,
                                                     __nv_bfloat16* __restrict__ l, int n) {
    int i = blockIdx.x * 256 + threadIdx.x;
    if (i < n) {
        __nv_bfloat16 hh, ll;
        bsplit(w[i], hh, ll);
        h[i] = hh; l[i] = ll;
    }
}

// ---------------------------------------------------------------------------
// Segment mean + transpose
// ---------------------------------------------------------------------------
__global__ void __launch_bounds__(256) mean_kernel(const float* __restrict__ data,
                                                   const int* __restrict__ rl) {
    __shared__ float tile[32][33];
    int g  = blockIdx.z;
    int c0 = blockIdx.y * 32;
    int l0 = blockIdx.x * 32;
    int start = 0;
    for (int gg = 0; gg < g; gg++) start += rl[gg];
    int cnt = rl[g];
    float inv = 1.0f / (float)cnt;
    int tx = threadIdx.x;
    for (int r = threadIdx.y; r < 32; r += 8) {
        float s = 0.0f;
        for (int a = 0; a < cnt; a++)
            s += data[((size_t)(start + a) * NC + (c0 + r)) * NL + l0 + tx];
        tile[r][tx] = s * inv;
    }
    __syncthreads();
    for (int r = threadIdx.y; r < 32; r += 8)
        g_x[((size_t)g * NL + (l0 + r)) * NC + c0 + tx] = tile[tx][r];
}

// ---------------------------------------------------------------------------
// LayerNorm
// ---------------------------------------------------------------------------
__device__ __forceinline__ void warp_stats8(const float* o, float& mu, float& rstd) {
    float s = 0.f, s2 = 0.f;
    #pragma unroll
    for (int i = 0; i < 8; i++) { s += o[i]; s2 += o[i] * o[i]; }
    #pragma unroll
    for (int off = 16; off; off >>= 1) {
        s  += __shfl_xor_sync(0xffffffffu, s, off);
        s2 += __shfl_xor_sync(0xffffffffu, s2, off);
    }
    mu = s * (1.0f / NC);
    float var = s2 * (1.0f / NC) - mu * mu;
    rstd = rsqrtf(var + 1e-5f);
}

// LN1 standalone (layer 0): g_x -> xnh/xnl
__global__ void __launch_bounds__(256) ln1_kernel(const float* __restrict__ w,
                                                  const float* __restrict__ b) {
    int row  = blockIdx.x * 8 + (threadIdx.x >> 5);
    int lane = threadIdx.x & 31;
    const float* xr = g_x + (size_t)row * NC + lane * 8;
    float v[8];
    *reinterpret_cast<float4*>(&v[0]) = *(const float4*)(xr);
    *reinterpret_cast<float4*>(&v[4]) = *(const float4*)(xr + 4);
    float mu, rstd;
    warp_stats8(v, mu, rstd);
    __nv_bfloat16 hh[8], ll[8];
    #pragma unroll
    for (int i = 0; i < 8; i++) {
        float o = (v[i] - mu) * rstd * w[lane * 8 + i] + b[lane * 8 + i];
        bsplit(o, hh[i], ll[i]);
    }
    uint4 vh = {pack2(hh[0],hh[1]), pack2(hh[2],hh[3]), pack2(hh[4],hh[5]), pack2(hh[6],hh[7])};
    uint4 vl = {pack2(ll[0],ll[1]), pack2(ll[2],ll[3]), pack2(ll[4],ll[5]), pack2(ll[6],ll[7])};
    *reinterpret_cast<uint4*>(g_xnh + (size_t)row * NC + lane * 8) = vh;
    *reinterpret_cast<uint4*>(g_xnl + (size_t)row * NC + lane * 8) = vl;
}

// Fused: LN2(g_gl)+residual -> g_x, then LN1(next layer) -> xnh/xnl
__global__ void __launch_bounds__(256) ln2ln1_kernel(const float* __restrict__ mw,
                                                     const float* __restrict__ mb,
                                                     const float* __restrict__ lw,
                                                     const float* __restrict__ lb) {
    int row  = blockIdx.x * 8 + (threadIdx.x >> 5);
    int lane = threadIdx.x & 31;
    const float* xr = g_gl + (size_t)row * NC + lane * 8;
    float v[8];
    *reinterpret_cast<float4*>(&v[0]) = *(const float4*)(xr);
    *reinterpret_cast<float4*>(&v[4]) = *(const float4*)(xr + 4);
    float mu, rstd;
    warp_stats8(v, mu, rstd);
    float* srow = g_x + (size_t)row * NC + lane * 8;
    float sk[8];
    *reinterpret_cast<float4*>(&sk[0]) = *(const float4*)(srow);
    *reinterpret_cast<float4*>(&sk[4]) = *(const float4*)(srow + 4);
    float nx[8];
    #pragma unroll
    for (int i = 0; i < 8; i++)
        nx[i] = (v[i] - mu) * rstd * mw[lane * 8 + i] + mb[lane * 8 + i] + sk[i];
    *(float4*)(srow)     = *reinterpret_cast<float4*>(&nx[0]);
    *(float4*)(srow + 4) = *reinterpret_cast<float4*>(&nx[4]);
    float mu2, rstd2;
    warp_stats8(nx, mu2, rstd2);
    __nv_bfloat16 hh[8], ll[8];
    #pragma unroll
    for (int i = 0; i < 8; i++) {
        float o = (nx[i] - mu2) * rstd2 * lw[lane * 8 + i] + lb[lane * 8 + i];
        bsplit(o, hh[i], ll[i]);
    }
    uint4 vh = {pack2(hh[0],hh[1]), pack2(hh[2],hh[3]), pack2(hh[4],hh[5]), pack2(hh[6],hh[7])};
    uint4 vl = {pack2(ll[0],ll[1]), pack2(ll[2],ll[3]), pack2(ll[4],ll[5]), pack2(ll[6],ll[7])};
    *reinterpret_cast<uint4*>(g_xnh + (size_t)row * NC + lane * 8) = vh;
    *reinterpret_cast<uint4*>(g_xnl + (size_t)row * NC + lane * 8) = vl;
}

// LN2 plain (last layer)
__global__ void __launch_bounds__(256) ln2_kernel(const float* __restrict__ w,
                                                  const float* __restrict__ b) {
    int row  = blockIdx.x * 8 + (threadIdx.x >> 5);
    int lane = threadIdx.x & 31;
    const float* xr = g_gl + (size_t)row * NC + lane * 8;
    float v[8];
    *reinterpret_cast<float4*>(&v[0]) = *(const float4*)(xr);
    *reinterpret_cast<float4*>(&v[4]) = *(const float4*)(xr + 4);
    float mu, rstd;
    warp_stats8(v, mu, rstd);
    float* srow = g_x + (size_t)row * NC + lane * 8;
    float sk[8];
    *reinterpret_cast<float4*>(&sk[0]) = *(const float4*)(srow);
    *reinterpret_cast<float4*>(&sk[4]) = *(const float4*)(srow + 4);
    float nx[8];
    #pragma unroll
    for (int i = 0; i < 8; i++)
        nx[i] = (v[i] - mu) * rstd * w[lane * 8 + i] + b[lane * 8 + i] + sk[i];
    *(float4*)(srow)     = *reinterpret_cast<float4*>(&nx[0]);
    *(float4*)(srow + 4) = *reinterpret_cast<float4*>(&nx[4]);
}

// ---------------------------------------------------------------------------
// Pipelined HMMA GEMM (pre-split bf16 A): C = A @ W^T, K=256
//   2-stage cp.async double buffer, dynamic smem.
//   Stage layout (pitch 80B rows): Ah[128][40] | Al[128][40] | Bh[NT][40] | Bl[NT][40]
// ---------------------------------------------------------------------------
template<int NT>
__global__ void __launch_bounds__(256) gemm_pre(const __nv_bfloat16* __restrict__ Ah,
                                                const __nv_bfloat16* __restrict__ Al,
                                                const __nv_bfloat16* __restrict__ Wh,
                                                const __nv_bfloat16* __restrict__ Wl,
                                                float* __restrict__ C, int ldc) {
    constexpr int WN   = (NT == 128) ? 32 : 8;
    constexpr int NSUB = WN / 8;
    constexpr int BOFF = 20480;
    constexpr int STG  = 20480 + 2 * NT * 80;
    extern __shared__ char dsm[];
    const uint32_t sb = smem_u32(dsm);

    const int tid = threadIdx.x, wid = tid >> 5, lane = tid & 31;
    const int l0 = blockIdx.x * 128, n0 = blockIdx.y * NT;
    const size_t aoff = (size_t)blockIdx.z * NL * NC;
    const int wm = (wid & 1) * 64;
    const int wn = (wid >> 1) * WN;
    const int arow = tid >> 1, ahalf = tid & 1;

    float acc[4][NSUB][4];
    #pragma unroll
    for (int mi = 0; mi < 4; mi++)
        #pragma unroll
        for (int ni = 0; ni < NSUB; ni++)
            #pragma unroll
            for (int q = 0; q < 4; q++) acc[mi][ni][q] = 0.0f;

    // stage issue: copy k-chunk kci into buffer buf
    auto issue = [&](int kci, int buf) {
        uint32_t base = sb + buf * STG;
        int kc = kci * 32;
        const __nv_bfloat16* ag = Ah + aoff + (size_t)(l0 + arow) * NC + kc + ahalf * 16;
        const __nv_bfloat16* alg = Al + aoff + (size_t)(l0 + arow) * NC + kc + ahalf * 16;
        uint32_t ad = base + arow * 80 + ahalf * 32;
        cp16(ad, ag);            cp16(ad + 16, ag + 8);
        cp16(ad + 10240, alg);   cp16(ad + 10240 + 16, alg + 8);
        if (NT == 128 || tid < NT * 2) {
            int brow = tid >> 1, bhalf = tid & 1;
            const __nv_bfloat16* bg  = Wh + (size_t)(n0 + brow) * NC + kc + bhalf * 16;
            const __nv_bfloat16* blg = Wl + (size_t)(n0 + brow) * NC + kc + bhalf * 16;
            uint32_t bd = base + BOFF + brow * 80 + bhalf * 32;
            cp16(bd, bg);             cp16(bd + 16, bg + 8);
            cp16(bd + NT * 80, blg);  cp16(bd + NT * 80 + 16, blg + 8);
        }
    };

    issue(0, 0);
    cp_commit();

    for (int kci = 0; kci < 8; kci++) {
        int buf = kci & 1;
        if (kci + 1 < 8) issue(kci + 1, buf ^ 1);
        cp_commit();
        cp_wait1();
        __syncthreads();
        uint32_t abase = sb + buf * STG;
        #pragma unroll
        for (int kk = 0; kk < 32; kk += 16) {
            uint32_t ah[4][4], al[4][4];
            #pragma unroll
            for (int mi = 0; mi < 4; mi++) {
                uint32_t ad = abase + (wm + mi * 16 + (lane & 15)) * 80 + (kk + (lane >> 4) * 8) * 2;
                ldsm_x4(ah[mi][0], ah[mi][1], ah[mi][2], ah[mi][3], ad);
                ldsm_x4(al[mi][0], al[mi][1], al[mi][2], al[mi][3], ad + 10240);
            }
            uint32_t bh[NSUB][2], bl[NSUB][2];
            #pragma unroll
            for (int ni = 0; ni < NSUB; ni++) {
                uint32_t bd = abase + BOFF + (wn + ni * 8 + (lane & 7)) * 80 + (kk + ((lane >> 3) & 1) * 8) * 2;
                ldsm_x2(bh[ni][0], bh[ni][1], bd);
                ldsm_x2(bl[ni][0], bl[ni][1], bd + NT * 80);
            }
            #pragma unroll
            for (int mi = 0; mi < 4; mi++)
                #pragma unroll
                for (int ni = 0; ni < NSUB; ni++) {
                    mma_bf16(acc[mi][ni], ah[mi], bh[ni]);
                    mma_bf16(acc[mi][ni], ah[mi], bl[ni]);
                    mma_bf16(acc[mi][ni], al[mi], bh[ni]);
                }
        }
        __syncthreads();
    }
    float* Cg = C + (size_t)blockIdx.z * NL * ldc;
    #pragma unroll
    for (int mi = 0; mi < 4; mi++)
        #pragma unroll
        for (int ni = 0; ni < NSUB; ni++) {
            int r = l0 + wm + mi * 16 + (lane >> 2);
            int c = n0 + wn + ni * 8 + (lane & 3) * 2;
            float2 v0 = {acc[mi][ni][0], acc[mi][ni][1]};
            float2 v1 = {acc[mi][ni][2], acc[mi][ni][3]};
            *reinterpret_cast<float2*>(Cg + (size_t)r * ldc + c)       = v0;
            *reinterpret_cast<float2*>(Cg + (size_t)(r + 8) * ldc + c) = v1;
        }
}

// ---------------------------------------------------------------------------
// out_proj GEMM with fused gating: A = 0.5*(y0+y1)*silu(z), split in-kernel.
// ---------------------------------------------------------------------------
__global__ void __launch_bounds__(256) gemm_gated(const float* __restrict__ Y0,
                                                  const float* __restrict__ Y1,
                                                  const float* __restrict__ XZ,
                                                  const __nv_bfloat16* __restrict__ Wh,
                                                  const __nv_bfloat16* __restrict__ Wl,
                                                  float* __restrict__ C, int ldc) {
    __shared__ __nv_bfloat16 Ah_s[128][40];
    __shared__ __nv_bfloat16 Al_s[128][40];
    __shared__ __nv_bfloat16 Bh_s[128][40];
    __shared__ __nv_bfloat16 Bl_s[128][40];

    const int tid = threadIdx.x, wid = tid >> 5, lane = tid & 31;
    const int l0 = blockIdx.x * 128, n0 = blockIdx.y * 128, g = blockIdx.z;
    const int wm = (wid & 1) * 64;
    const int wn = (wid >> 1) * 32;
    const int arow = tid >> 1, ahalf = tid & 1;

    float acc[4][4][4];
    #pragma unroll
    for (int mi = 0; mi < 4; mi++)
        #pragma unroll
        for (int ni = 0; ni < 4; ni++)
            #pragma unroll
            for (int q = 0; q < 4; q++) acc[mi][ni][q] = 0.0f;

    for (int kc = 0; kc < NC; kc += 32) {
        // stage A: gated y
        {
            const float* y0 = Y0 + (size_t)g * NL * NC + (size_t)(l0 + arow) * NC + kc + ahalf * 16;
            const float* y1 = Y1 + (size_t)g * NL * NC + (size_t)(l0 + arow) * NC + kc + ahalf * 16;
            const float* zp = XZ + (size_t)g * NL * 512 + (size_t)(l0 + arow) * 512 + 256 + kc + ahalf * 16;
            float f[16];
            #pragma unroll
            for (int q = 0; q < 4; q++) {
                float4 a0 = *reinterpret_cast<const float4*>(y0 + q * 4);
                float4 a1 = *reinterpret_cast<const float4*>(y1 + q * 4);
                float4 zz = *reinterpret_cast<const float4*>(zp + q * 4);
                f[q*4+0] = 0.5f * (a0.x + a1.x) * (zz.x / (1.0f + __expf(-zz.x)));
                f[q*4+1] = 0.5f * (a0.y + a1.y) * (zz.y / (1.0f + __expf(-zz.y)));
                f[q*4+2] = 0.5f * (a0.z + a1.z) * (zz.z / (1.0f + __expf(-zz.z)));
                f[q*4+3] = 0.5f * (a0.w + a1.w) * (zz.w / (1.0f + __expf(-zz.w)));
            }
            __nv_bfloat16 hh[16], ll[16];
            #pragma unroll
            for (int j = 0; j < 16; j++) bsplit(f[j], hh[j], ll[j]);
            uint4 vh0 = {pack2(hh[0],hh[1]),  pack2(hh[2],hh[3]),  pack2(hh[4],hh[5]),  pack2(hh[6],hh[7])};
            uint4 vh1 = {pack2(hh[8],hh[9]),  pack2(hh[10],hh[11]),pack2(hh[12],hh[13]),pack2(hh[14],hh[15])};
            uint4 vl0 = {pack2(ll[0],ll[1]),  pack2(ll[2],ll[3]),  pack2(ll[4],ll[5]),  pack2(ll[6],ll[7])};
            uint4 vl1 = {pack2(ll[8],ll[9]),  pack2(ll[10],ll[11]),pack2(ll[12],ll[13]),pack2(ll[14],ll[15])};
            *reinterpret_cast<uint4*>(&Ah_s[arow][ahalf * 16])     = vh0;
            *reinterpret_cast<uint4*>(&Ah_s[arow][ahalf * 16 + 8]) = vh1;
            *reinterpret_cast<uint4*>(&Al_s[arow][ahalf * 16])     = vl0;
            *reinterpret_cast<uint4*>(&Al_s[arow][ahalf * 16 + 8]) = vl1;
        }
        // stage B
        {
            const __nv_bfloat16* bg  = Wh + (size_t)(n0 + arow) * NC + kc + ahalf * 16;
            const __nv_bfloat16* blg = Wl + (size_t)(n0 + arow) * NC + kc + ahalf * 16;
            uint4 h0 = *reinterpret_cast<const uint4*>(bg);
            uint4 h1 = *reinterpret_cast<const uint4*>(bg + 8);
            uint4 l0v = *reinterpret_cast<const uint4*>(blg);
            uint4 l1v = *reinterpret_cast<const uint4*>(blg + 8);
            *reinterpret_cast<uint4*>(&Bh_s[arow][ahalf * 16])     = h0;
            *reinterpret_cast<uint4*>(&Bh_s[arow][ahalf * 16 + 8]) = h1;
            *reinterpret_cast<uint4*>(&Bl_s[arow][ahalf * 16])     = l0v;
            *reinterpret_cast<uint4*>(&Bl_s[arow][ahalf * 16 + 8]) = l1v;
        }
        __syncthreads();
        #pragma unroll
        for (int kk = 0; kk < 32; kk += 16) {
            uint32_t ah[4][4], al[4][4];
            #pragma unroll
            for (int mi = 0; mi < 4; mi++) {
                uint32_t ad = smem_u32(&Ah_s[wm + mi * 16 + (lane & 15)][kk + (lane >> 4) * 8]);
                ldsm_x4(ah[mi][0], ah[mi][1], ah[mi][2], ah[mi][3], ad);
                ad = smem_u32(&Al_s[wm + mi * 16 + (lane & 15)][kk + (lane >> 4) * 8]);
                ldsm_x4(al[mi][0], al[mi][1], al[mi][2], al[mi][3], ad);
            }
            uint32_t bh[4][2], bl[4][2];
            #pragma unroll
            for (int ni = 0; ni < 4; ni++) {
                uint32_t bd = smem_u32(&Bh_s[wn + ni * 8 + (lane & 7)][kk + ((lane >> 3) & 1) * 8]);
                ldsm_x2(bh[ni][0], bh[ni][1], bd);
                bd = smem_u32(&Bl_s[wn + ni * 8 + (lane & 7)][kk + ((lane >> 3) & 1) * 8]);
                ldsm_x2(bl[ni][0], bl[ni][1], bd);
            }
            #pragma unroll
            for (int mi = 0; mi < 4; mi++)
                #pragma unroll
                for (int ni = 0; ni < 4; ni++) {
                    mma_bf16(acc[mi][ni], ah[mi], bh[ni]);
                    mma_bf16(acc[mi][ni], ah[mi], bl[ni]);
                    mma_bf16(acc[mi][ni], al[mi], bh[ni]);
                }
        }
        __syncthreads();
    }
    float* Cg = C + (size_t)g * NL * ldc;
    #pragma unroll
    for (int mi = 0; mi < 4; mi++)
        #pragma unroll
        for (int ni = 0; ni < 4; ni++) {
            int r = l0 + wm + mi * 16 + (lane >> 2);
            int c = n0 + wn + ni * 8 + (lane & 3) * 2;
            float2 v0 = {acc[mi][ni][0], acc[mi][ni][1]};
            float2 v1 = {acc[mi][ni][2], acc[mi][ni][3]};
            *reinterpret_cast<float2*>(Cg + (size_t)r * ldc + c)       = v0;
            *reinterpret_cast<float2*>(Cg + (size_t)(r + 8) * ldc + c) = v1;
        }
}

// ---------------------------------------------------------------------------
// conv(k=4 causal) + SiLU -> bf16 hi/lo pair
// ---------------------------------------------------------------------------
__global__ void __launch_bounds__(256) conv_silu_kernel(const float* __restrict__ cw,
                                                        const float* __restrict__ cb) {
    int d  = threadIdx.x;
    int l0 = blockIdx.x * 8;
    int dg = blockIdx.y;
    int dir = dg >> 3, g = dg & 7;
    float4 wv = *reinterpret_cast<const float4*>(cw + d * 4);
    float bias = cb[d];
    const float* X = g_xz + (size_t)g * NL * (2 * NC) + d;
    float x0 = 0.f, x1 = 0.f, x2 = 0.f;
    {
        int lj;
        lj = l0 - 3; if (lj >= 0) x0 = X[(size_t)(dir ? (NL - 1 - lj) : lj) * (2 * NC)];
        lj = l0 - 2; if (lj >= 0) x1 = X[(size_t)(dir ? (NL - 1 - lj) : lj) * (2 * NC)];
        lj = l0 - 1; if (lj >= 0) x2 = X[(size_t)(dir ? (NL - 1 - lj) : lj) * (2 * NC)];
    }
    __nv_bfloat16* oh = g_xch + ((size_t)dg * NL + l0) * NC + d;
    __nv_bfloat16* ol = g_xcl + ((size_t)dg * NL + l0) * NC + d;
    #pragma unroll
    for (int i = 0; i < 8; i++) {
        int l = l0 + i;
        int src = dir ? (NL - 1 - l) : l;
        float x3 = X[(size_t)src * (2 * NC)];
        float s = bias;
        s = fmaf(wv.x, x0, s); s = fmaf(wv.y, x1, s);
        s = fmaf(wv.z, x2, s); s = fmaf(wv.w, x3, s);
        float v = s / (1.0f + __expf(-s));
        __nv_bfloat16 hh, ll;
        bsplit(v, hh, ll);
        oh[(size_t)i * NC] = hh;
        ol[(size_t)i * NC] = ll;
        x0 = x1; x1 = x2; x2 = x3;
    }
}

// ---------------------------------------------------------------------------
// Fused scan (dt_proj + softplus + selective scan)
// ---------------------------------------------------------------------------
__device__ __forceinline__ float softplusf(float s) {
    return (s > 20.0f) ? s : log1pf(__expf(s));
}

__global__ void __launch_bounds__(256) scan_pass1_kernel(const float* __restrict__ Wdt,
                                                         const float* __restrict__ dtb,
                                                         const float* __restrict__ AlogF,
                                                         const float* __restrict__ AlogB) {
    __shared__ float sm[CHUNK * 36];
    const int d  = threadIdx.x;
    const int ck = blockIdx.x;
    const int dg = blockIdx.y;
    const int dir = dg >> 3;
    {
        const float* xd = g_xdbl + ((size_t)dg * NL + ck * CHUNK) * NEDBL;
        #pragma unroll
        for (int it = 0; it < 4; it++) {
            int flat = threadIdx.x + it * 256;
            int row = flat >> 3, c4 = flat & 7;
            float4 v = *reinterpret_cast<const float4*>(xd + (size_t)row * NEDBL + c4 * 4);
            *reinterpret_cast<float4*>(&sm[row * 36 + c4 * 4]) = v;
        }
    }
    __syncthreads();
    const float* Alog = (dir ? AlogB : AlogF) + d * NST;
    float A[NST];
    #pragma unroll
    for (int n = 0; n < NST; n++) A[n] = -__expf(Alog[n]);
    float Wr[NRK];
    #pragma unroll
    for (int q = 0; q < 4; q++) {
        float4 v = *reinterpret_cast<const float4*>(Wdt + d * NRK + q * 4);
        Wr[q * 4] = v.x; Wr[q * 4 + 1] = v.y; Wr[q * 4 + 2] = v.z; Wr[q * 4 + 3] = v.w;
    }
    float bias = dtb[d];
    const __nv_bfloat16* uh = g_xch + ((size_t)dg * NL + ck * CHUNK) * NC + d;
    const __nv_bfloat16* ul = g_xcl + ((size_t)dg * NL + ck * CHUNK) * NC + d;
    float h[NST], ap[NST];
    #pragma unroll
    for (int n = 0; n < NST; n++) { h[n] = 0.0f; ap[n] = 1.0f; }
    for (int t = 0; t < CHUNK; t++) {
        const float* srow = sm + t * 36;
        float s = bias;
        #pragma unroll
        for (int r = 0; r < NRK; r++) s = fmaf(Wr[r], srow[r], s);
        float dl = softplusf(s);
        float u = __bfloat162float(uh[(size_t)t * NC]) + __bfloat162float(ul[(size_t)t * NC]);
        float du = dl * u;
        #pragma unroll
        for (int n = 0; n < NST; n++) {
            float a = __expf(dl * A[n]);
            ap[n] *= a;
            h[n] = fmaf(a, h[n], du * srow[NRK + n]);
        }
    }
    float* apO = g_ap   + (((size_t)dg * NCHUNK + ck) * NST) * NC + d;
    float* heO = g_hend + (((size_t)dg * NCHUNK + ck) * NST) * NC + d;
    #pragma unroll
    for (int n = 0; n < NST; n++) { apO[n * NC] = ap[n]; heO[n * NC] = h[n]; }
}

__global__ void __launch_bounds__(256) scan_combine_kernel() {
    int idx = blockIdx.x * 256 + threadIdx.x;
    int d  = idx & (NC - 1);
    int n  = (idx >> 8) & 7;
    int dg = idx >> 11;
    size_t base = ((size_t)dg * NCHUNK * NST + n) * NC + d;
    float h = 0.0f;
    for (int k = 0; k < NCHUNK; k++) {
        size_t o = base + (size_t)k * NST * NC;
        g_hin[o] = h;
        h = g_ap[o] * h + g_hend[o];
    }
}

// pass2: raw y (incl. D*u), per-direction buffer, no gating
__global__ void __launch_bounds__(256) scan_pass2_kernel(int dir,
                                                         const float* __restrict__ Wdt,
                                                         const float* __restrict__ dtb,
                                                         const float* __restrict__ Alog,
                                                         const float* __restrict__ Dp,
                                                         float* __restrict__ Yout) {
    __shared__ float sm[CHUNK * 36];
    const int d  = threadIdx.x;
    const int ck = blockIdx.x;
    const int g  = blockIdx.y;
    const int dg = dir * NG + g;
    {
        const float* xd = g_xdbl + ((size_t)dg * NL + ck * CHUNK) * NEDBL;
        #pragma unroll
        for (int it = 0; it < 4; it++) {
            int flat = threadIdx.x + it * 256;
            int row = flat >> 3, c4 = flat & 7;
            float4 v = *reinterpret_cast<const float4*>(xd + (size_t)row * NEDBL + c4 * 4);
            *reinterpret_cast<float4*>(&sm[row * 36 + c4 * 4]) = v;
        }
    }
    __syncthreads();
    float A[NST];
    #pragma unroll
    for (int n = 0; n < NST; n++) A[n] = -__expf(Alog[d * NST + n]);
    float Wr[NRK];
    #pragma unroll
    for (int q = 0; q < 4; q++) {
        float4 v = *reinterpret_cast<const float4*>(Wdt + d * NRK + q * 4);
        Wr[q * 4] = v.x; Wr[q * 4 + 1] = v.y; Wr[q * 4 + 2] = v.z; Wr[q * 4 + 3] = v.w;
    }
    float bias = dtb[d];
    float Dd = Dp[d];
    const __nv_bfloat16* uh = g_xch + ((size_t)dg * NL + ck * CHUNK) * NC + d;
    const __nv_bfloat16* ul = g_xcl + ((size_t)dg * NL + ck * CHUNK) * NC + d;
    const float* hiP = g_hin + (((size_t)dg * NCHUNK + ck) * NST) * NC + d;
    float h[NST];
    #pragma unroll
    for (int n = 0; n < NST; n++) h[n] = hiP[n * NC];
    for (int t = 0; t < CHUNK; t++) {
        const float* srow = sm + t * 36;
        float s = bias;
        #pragma unroll
        for (int r = 0; r < NRK; r++) s = fmaf(Wr[r], srow[r], s);
        float dl = softplusf(s);
        float u = __bfloat162float(uh[(size_t)t * NC]) + __bfloat162float(ul[(size_t)t * NC]);
        float du = dl * u;
        float accv = 0.0f;
        #pragma unroll
        for (int n = 0; n < NST; n++) {
            float a = __expf(dl * A[n]);
            h[n] = fmaf(a, h[n], du * srow[NRK + n]);
            accv = fmaf(h[n], srow[NRK + NST + n], accv);
        }
        float yv = fmaf(Dd, u, accv);
        int l  = ck * CHUNK + t;
        int lo = dir ? (NL - 1 - l) : l;
        Yout[((size_t)g * NL + lo) * NC + d] = yv;
    }
}

// ---------------------------------------------------------------------------
// final transpose
// ---------------------------------------------------------------------------
__global__ void __launch_bounds__(256) out_transpose_kernel(float* __restrict__ out) {
    __shared__ float tile[32][33];
    int g  = blockIdx.z;
    int c0 = blockIdx.y * 32;
    int l0 = blockIdx.x * 32;
    int tx = threadIdx.x;
    for (int r = threadIdx.y; r < 32; r += 8)
        tile[r][tx] = g_x[((size_t)g * NL + (l0 + r)) * NC + c0 + tx];
    __syncthreads();
    for (int r = threadIdx.y; r < 32; r += 8)
        out[((size_t)g * NC + (c0 + r)) * NL + l0 + tx] = tile[tx][r];
}

// ---------------------------------------------------------------------------
// Launch
// ---------------------------------------------------------------------------
extern "C" void kernel_launch(void* const* d_in, const int* in_sizes, int n_in,
                              void* d_out, int out_size) {
    const float* data       = (const float*)d_in[0];
    const float* ln_w       = (const float*)d_in[1];
    const float* ln_b       = (const float*)d_in[2];
    const float* in_proj_w  = (const float*)d_in[3];
    const float* conv_w     = (const float*)d_in[4];
    const float* conv_b     = (const float*)d_in[5];
    const float* x_proj_w   = (const float*)d_in[6];
    const float* dt_proj_w  = (const float*)d_in[7];
    const float* dt_proj_b  = (const float*)d_in[8];
    const float* A_log      = (const float*)d_in[9];
    const float* A_b_log    = (const float*)d_in[10];
    const float* Dparam     = (const float*)d_in[11];
    const float* out_proj_w = (const float*)d_in[12];
    const float* mn_w       = (const float*)d_in[13];
    const float* mn_b       = (const float*)d_in[14];
    const int*   record_len = (const int*)d_in[15];
    float* out = (float*)d_out;

    float *d_xz, *d_xdbl, *d_y0, *d_y1, *d_gl;
    cudaGetSymbolAddress((void**)&d_xz,  g_xz);
    cudaGetSymbolAddress((void**)&d_xdbl,g_xdbl);
    cudaGetSymbolAddress((void**)&d_y0,  g_y0);
    cudaGetSymbolAddress((void**)&d_y1,  g_y1);
    cudaGetSymbolAddress((void**)&d_gl,  g_gl);
    __nv_bfloat16 *d_xnh, *d_xnl, *d_xch, *d_xcl;
    __nv_bfloat16 *d_wih, *d_wil, *d_wxh, *d_wxl, *d_woh, *d_wol;
    cudaGetSymbolAddress((void**)&d_xnh, g_xnh);
    cudaGetSymbolAddress((void**)&d_xnl, g_xnl);
    cudaGetSymbolAddress((void**)&d_xch, g_xch);
    cudaGetSymbolAddress((void**)&d_xcl, g_xcl);
    cudaGetSymbolAddress((void**)&d_wih, g_wih);
    cudaGetSymbolAddress((void**)&d_wil, g_wil);
    cudaGetSymbolAddress((void**)&d_wxh, g_wxh);
    cudaGetSymbolAddress((void**)&d_wxl, g_wxl);
    cudaGetSymbolAddress((void**)&d_woh, g_woh);
    cudaGetSymbolAddress((void**)&d_wol, g_wol);

    static bool attrs_set = false;
    if (!attrs_set) {
        cudaFuncSetAttribute(gemm_pre<128>, cudaFuncAttributeMaxDynamicSharedMemorySize, 81920);
        cudaFuncSetAttribute(gemm_pre<32>,  cudaFuncAttributeMaxDynamicSharedMemorySize, 51200);
        attrs_set = true;
    }

    wsplit_kernel<<<(NDEPTH * 512 * NC + 255) / 256, 256>>>(in_proj_w,  d_wih, d_wil, NDEPTH * 512 * NC);
    wsplit_kernel<<<(NDEPTH * NEDBL * NC + 255) / 256, 256>>>(x_proj_w,  d_wxh, d_wxl, NDEPTH * NEDBL * NC);
    wsplit_kernel<<<(NDEPTH * NC * NC + 255) / 256, 256>>>(out_proj_w, d_woh, d_wol, NDEPTH * NC * NC);

    mean_kernel<<<dim3(NL / 32, NC / 32, NG), dim3(32, 8)>>>(data, record_len);
    ln1_kernel<<<NG * NL / 8, 256>>>(ln_w, ln_b);   // layer 0

    for (int i = 0; i < NDEPTH; i++) {
        gemm_pre<128><<<dim3(NL / 128, 4, NG), 256, 81920>>>(
            d_xnh, d_xnl, d_wih + (size_t)i * 512 * NC, d_wil + (size_t)i * 512 * NC, d_xz, 512);
        conv_silu_kernel<<<dim3(NL / 8, 2 * NG), 256>>>(conv_w + i * NC * 4, conv_b + i * NC);
        gemm_pre<32><<<dim3(NL / 128, 1, 2 * NG), 256, 51200>>>(
            d_xch, d_xcl, d_wxh + (size_t)i * NEDBL * NC, d_wxl + (size_t)i * NEDBL * NC, d_xdbl, NEDBL);
        scan_pass1_kernel<<<dim3(NCHUNK, 2 * NG), 256>>>(
            dt_proj_w + (size_t)i * NC * NRK, dt_proj_b + i * NC,
            A_log + (size_t)i * NC * NST, A_b_log + (size_t)i * NC * NST);
        scan_combine_kernel<<<(2 * NG * NST * NC) / 256, 256>>>();
        scan_pass2_kernel<<<dim3(NCHUNK, NG), 256>>>(0,
            dt_proj_w + (size_t)i * NC * NRK, dt_proj_b + i * NC,
            A_log + (size_t)i * NC * NST, Dparam + i * NC, d_y0);
        scan_pass2_kernel<<<dim3(NCHUNK, NG), 256>>>(1,
            dt_proj_w + (size_t)i * NC * NRK, dt_proj_b + i * NC,
            A_b_log + (size_t)i * NC * NST, Dparam + i * NC, d_y1);
        gemm_gated<<<dim3(NL / 128, 2, NG), 256>>>(
            d_y0, d_y1, d_xz, d_woh + (size_t)i * NC * NC, d_wol + (size_t)i * NC * NC, d_gl, 256);
        if (i < NDEPTH - 1)
            ln2ln1_kernel<<<NG * NL / 8, 256>>>(mn_w + i * NC, mn_b + i * NC,
                                                ln_w + (i + 1) * NC, ln_b + (i + 1) * NC);
        else
            ln2_kernel<<<NG * NL / 8, 256>>>(mn_w + i * NC, mn_b + i * NC);
    }

    out_transpose_kernel<<<dim3(NL / 32, NC / 32, NG), dim3(32, 8)>>>(out);
}